// round 1
// baseline (speedup 1.0000x reference)
#include <cuda_runtime.h>
#include <cuda_bf16.h>
#include <math.h>

// ---------------- problem constants ----------------
#define BB 2
#define TT 1024
#define CC 4096
#define NH 32
#define HS 128
#define ALEN 10
#define AT 1500
#define AD 1280
#define NWH 20
#define WHD 64
#define DHID 80           // AD/16
#define ATT_SCALE 0.08838834764831845f   // 1/sqrt(128)

// ---------------- scratch buffers (device globals; no allocation) ----------------
__device__ float g_qkv [BB*TT*3*CC];        // 25.2M
__device__ float g_q   [BB*NH*TT*HS];
__device__ float g_k   [BB*NH*TT*HS];
__device__ float g_v   [BB*NH*TT*HS];
__device__ float g_y   [BB*NH*TT*HS];
__device__ float g_pref[ALEN*CC];
__device__ float g_aqkv[ALEN*3*CC];
__device__ float g_ak  [NH*ALEN*HS];
__device__ float g_av  [NH*ALEN*HS];
__device__ float g_wkn [BB*AT*AD];
__device__ float g_wvn [BB*AT*AD];
__device__ float g_hid [BB*AT*DHID];
__device__ float g_wk  [BB*AT*AD];
__device__ float g_wv  [BB*AT*AD];
__device__ float g_pk  [BB*NH*AT*HS];       // 12.3M
__device__ float g_pv  [BB*NH*AT*HS];
__device__ float g_q2a [BB*NH*TT*HS];
__device__ float g_q2  [BB*NH*TT*HS];
__device__ float g_ybt [BB*TT*CC];

// ---------------- generic 128x128x8 SGEMM, row-major A[M,K] @ B[K,N] ----------------
// act: 0 = none, 1 = silu.  bias (len N) optional.
__global__ __launch_bounds__(256) void sgemm_kernel(
    const float* __restrict__ A, const float* __restrict__ B, float* __restrict__ C,
    int M, int N, int K, const float* __restrict__ bias, int act)
{
    __shared__ float As[8][128];
    __shared__ float Bs[8][128];
    const int bm = blockIdx.y, bn = blockIdx.x;
    const int tid = threadIdx.x;
    const int ty = tid >> 4, tx = tid & 15;

    float acc[8][8];
#pragma unroll
    for (int i = 0; i < 8; i++)
#pragma unroll
        for (int j = 0; j < 8; j++) acc[i][j] = 0.f;

    const int row_a = tid >> 1;          // 0..127
    const int ka4   = (tid & 1) * 4;     // 0 or 4
    const int row_b = tid >> 5;          // 0..7
    const int cb4   = (tid & 31) * 4;    // 0..124
    const int arow_g = bm * 128 + row_a;
    const int bcol_g = bn * 128 + cb4;

    for (int kt = 0; kt < K; kt += 8) {
        float4 av = make_float4(0.f, 0.f, 0.f, 0.f);
        if (arow_g < M)
            av = *(const float4*)&A[(long)arow_g * K + kt + ka4];
        As[ka4 + 0][row_a] = av.x;
        As[ka4 + 1][row_a] = av.y;
        As[ka4 + 2][row_a] = av.z;
        As[ka4 + 3][row_a] = av.w;

        float4 bv = make_float4(0.f, 0.f, 0.f, 0.f);
        if (bcol_g + 3 < N)
            bv = *(const float4*)&B[(long)(kt + row_b) * N + bcol_g];
        *(float4*)&Bs[row_b][cb4] = bv;
        __syncthreads();

#pragma unroll
        for (int kk = 0; kk < 8; kk++) {
            float a[8], b[8];
            *(float4*)&a[0] = *(const float4*)&As[kk][ty * 8];
            *(float4*)&a[4] = *(const float4*)&As[kk][ty * 8 + 4];
            *(float4*)&b[0] = *(const float4*)&Bs[kk][tx * 8];
            *(float4*)&b[4] = *(const float4*)&Bs[kk][tx * 8 + 4];
#pragma unroll
            for (int i = 0; i < 8; i++)
#pragma unroll
                for (int j = 0; j < 8; j++)
                    acc[i][j] = fmaf(a[i], b[j], acc[i][j]);
        }
        __syncthreads();
    }

#pragma unroll
    for (int i = 0; i < 8; i++) {
        int gr = bm * 128 + ty * 8 + i;
        if (gr >= M) continue;
#pragma unroll
        for (int j = 0; j < 8; j++) {
            int gc = bn * 128 + tx * 8 + j;
            if (gc < N) {
                float v = acc[i][j];
                if (bias) v += bias[gc];
                if (act == 1) v = v / (1.f + __expf(-v));   // silu
                C[(long)gr * N + gc] = v;
            }
        }
    }
}

// ---------------- rmsnorm per row (blockDim = 256) ----------------
__global__ void rmsnorm_kernel(const float* __restrict__ in, const float* __restrict__ w,
                               float* __restrict__ out, int N)
{
    int row = blockIdx.x;
    const float* x = in + (long)row * N;
    float ss = 0.f;
    for (int c = threadIdx.x; c < N; c += 256) { float v = x[c]; ss = fmaf(v, v, ss); }
    __shared__ float sh[32];
    int lane = threadIdx.x & 31, wid = threadIdx.x >> 5;
#pragma unroll
    for (int o = 16; o; o >>= 1) ss += __shfl_xor_sync(0xffffffffu, ss, o);
    if (lane == 0) sh[wid] = ss;
    __syncthreads();
    float tot = (threadIdx.x < 8) ? sh[threadIdx.x] : 0.f;
    if (wid == 0) {
#pragma unroll
        for (int o = 16; o; o >>= 1) tot += __shfl_xor_sync(0xffffffffu, tot, o);
    }
    __shared__ float ssc;
    if (threadIdx.x == 0) ssc = rsqrtf(tot / (float)N + 1e-5f);
    __syncthreads();
    float sc = ssc;
    float* o = out + (long)row * N;
    for (int c = threadIdx.x; c < N; c += 256) o[c] = x[c] * sc * w[c];
}

// ---------------- split qkv + rope -> q,k,v in [B,NH,T,HS] ----------------
__global__ void split_rope_kernel(const float* __restrict__ qkv,
                                  const float* __restrict__ cos_, const float* __restrict__ sin_,
                                  float* __restrict__ q, float* __restrict__ k, float* __restrict__ v)
{
    int idx = blockIdx.x * blockDim.x + threadIdx.x;        // B*T*NH*64
    if (idx >= BB * TT * NH * 64) return;
    int i = idx & 63;
    int h = (idx >> 6) & 31;
    int t = (idx >> 11) & 1023;
    int b = idx >> 21;
    long base = ((long)(b * TT + t)) * (3 * CC) + h * HS + 2 * i;
    float q0 = qkv[base],        q1 = qkv[base + 1];
    float k0 = qkv[base + CC],   k1 = qkv[base + CC + 1];
    float v0 = qkv[base + 2*CC], v1 = qkv[base + 2*CC + 1];
    float c = cos_[t * 64 + i], s = sin_[t * 64 + i];
    long ob = ((long)((b * NH + h) * TT + t)) * HS + 2 * i;
    q[ob] = q0 * c - q1 * s;  q[ob + 1] = q1 * c + q0 * s;
    k[ob] = k0 * c - k1 * s;  k[ob + 1] = k1 * c + k0 * s;
    v[ob] = v0;               v[ob + 1] = v1;
}

// ---------------- adapter k/v split: aqkv[10, 3C] -> ak/av [NH, 10, HS] ----------------
__global__ void adapter_split_kernel(const float* __restrict__ aqkv,
                                     float* __restrict__ ak, float* __restrict__ av)
{
    int idx = blockIdx.x * blockDim.x + threadIdx.x;   // NH*ALEN*HS
    if (idx >= NH * ALEN * HS) return;
    int d = idx & 127;
    int a = (idx >> 7) % ALEN;
    int h = idx / (ALEN * HS);
    ak[idx] = aqkv[(long)a * (3 * CC) + CC     + h * HS + d];
    av[idx] = aqkv[(long)a * (3 * CC) + 2 * CC + h * HS + d];
}

// ---------------- assemble pk/pv: [B,NH,AT,HS] ----------------
// wflat is the flat (B, AT*AD) buffer; reshape (B,20,1500,64) is flat-index identical.
__global__ void fill_pkv_kernel(const float* __restrict__ wflat, const float* __restrict__ pad,
                                float* __restrict__ pkv)
{
    int idx = blockIdx.x * blockDim.x + threadIdx.x;   // B*NH*AT*HS
    if (idx >= BB * NH * AT * HS) return;
    int d = idx & 127;
    int t = (idx >> 7) % AT;
    int h = (idx / (HS * AT)) & 31;
    int b = idx / (HS * AT * NH);
    float v;
    if (h < NWH && d < WHD)
        v = wflat[(long)b * (AT * AD) + h * (AT * WHD) + t * WHD + d];
    else
        v = pad[((long)b * AT + t) * HS + d];
    pkv[idx] = v;
}

// ---------------- head mix: q2[b,g,t,:] = sum_h q2a[b,h,t,:] * w[h,g] ----------------
__global__ __launch_bounds__(256) void headmix_kernel(const float* __restrict__ q2a,
                                                      const float* __restrict__ w,
                                                      float* __restrict__ q2)
{
    int bt = blockIdx.x;
    int b = bt >> 10, t = bt & 1023;
    __shared__ float sm[NH * HS];
    __shared__ float ws[NH * NH];
    for (int i = threadIdx.x; i < NH * HS; i += 256) {
        int h = i >> 7, d = i & 127;
        sm[i] = q2a[(((long)(b * NH + h)) * TT + t) * HS + d];
    }
    for (int i = threadIdx.x; i < NH * NH; i += 256) ws[i] = w[i];
    __syncthreads();
    for (int i = threadIdx.x; i < NH * HS; i += 256) {
        int g = i >> 7, d = i & 127;
        float acc = 0.f;
#pragma unroll
        for (int h = 0; h < NH; h++) acc = fmaf(sm[h * HS + d], ws[h * NH + g], acc);
        q2[(((long)(b * NH + g)) * TT + t) * HS + d] = acc;
    }
}

// ---------------- [B,NH,T,HS] -> [B,T,C] ----------------
__global__ void transpose_y_kernel(const float* __restrict__ y, float* __restrict__ out)
{
    int idx = blockIdx.x * blockDim.x + threadIdx.x;   // B*T*C
    if (idx >= BB * TT * CC) return;
    int d = idx & 127;
    int h = (idx >> 7) & 31;
    int t = (idx >> 12) & 1023;
    int b = idx >> 22;
    out[idx] = y[(((long)(b * NH + h)) * TT + t) * HS + d];
}

// ---------------- flash-style attention ----------------
// Q [B,H,Tq,128]; K/V element at b*kvbs + h*kvhs + t*128 + d (kvbs=0 broadcasts over b).
// Out [B,H,Tq,128]; accum: Out += gate*attn, else Out = attn.
// Block: 256 thr / 8 warps, 32 queries per block (4 per warp), 32-key tiles.
__global__ __launch_bounds__(256) void attn_kernel(
    const float* __restrict__ Q, const float* __restrict__ K, const float* __restrict__ V,
    float* __restrict__ Out, int H, int Tq, int Tk,
    long kvbs, long kvhs, int causal, const float* __restrict__ gatep, int accum)
{
    __shared__ float Qs[32 * 128];
    __shared__ float Ks[32 * 128];   // XOR-swizzled float4 columns
    __shared__ float Vs[32 * 128];
    const int qt = blockIdx.x, h = blockIdx.y, b = blockIdx.z;
    const int tid = threadIdx.x, warp = tid >> 5, lane = tid & 31;
    const int q0 = qt * 32;
    const long qbase = ((long)(b * H + h)) * Tq * 128;

    for (int i = tid; i < 32 * 32; i += 256) {
        int r = i >> 5, c4 = i & 31;
        float4 val = make_float4(0.f, 0.f, 0.f, 0.f);
        if (q0 + r < Tq)
            val = *(const float4*)&Q[qbase + (long)(q0 + r) * 128 + c4 * 4];
        *(float4*)&Qs[r * 128 + c4 * 4] = val;
    }

    float m[4], l[4];
    float4 acc[4];
#pragma unroll
    for (int qq = 0; qq < 4; qq++) { m[qq] = -1e30f; l[qq] = 0.f; acc[qq] = make_float4(0,0,0,0); }

    const long kbase = (long)b * kvbs + (long)h * kvhs;
    const int kend = causal ? min(Tk, q0 + 32) : Tk;

    for (int kt = 0; kt < kend; kt += 32) {
        __syncthreads();
        for (int i = tid; i < 32 * 32; i += 256) {
            int r = i >> 5, c4 = i & 31;
            float4 kv = make_float4(0,0,0,0), vv = make_float4(0,0,0,0);
            if (kt + r < Tk) {
                long off = kbase + (long)(kt + r) * 128 + c4 * 4;
                kv = *(const float4*)&K[off];
                vv = *(const float4*)&V[off];
            }
            *(float4*)&Ks[r * 128 + ((c4 ^ r) & 31) * 4] = kv;   // swizzle
            *(float4*)&Vs[r * 128 + c4 * 4] = vv;
        }
        __syncthreads();

        float s[4] = {0.f, 0.f, 0.f, 0.f};
#pragma unroll
        for (int c = 0; c < 32; c += 4) {
            float4 k0 = *(const float4*)&Ks[lane * 128 + (((c + 0) ^ lane) & 31) * 4];
            float4 k1 = *(const float4*)&Ks[lane * 128 + (((c + 1) ^ lane) & 31) * 4];
            float4 k2 = *(const float4*)&Ks[lane * 128 + (((c + 2) ^ lane) & 31) * 4];
            float4 k3 = *(const float4*)&Ks[lane * 128 + (((c + 3) ^ lane) & 31) * 4];
#pragma unroll
            for (int qq = 0; qq < 4; qq++) {
                const float* qr = &Qs[(warp * 4 + qq) * 128 + c * 4];
                float4 a0 = *(const float4*)&qr[0];
                float4 a1 = *(const float4*)&qr[4];
                float4 a2 = *(const float4*)&qr[8];
                float4 a3 = *(const float4*)&qr[12];
                float t0;
                t0  = a0.x * k0.x + a0.y * k0.y + a0.z * k0.z + a0.w * k0.w;
                t0 += a1.x * k1.x + a1.y * k1.y + a1.z * k1.z + a1.w * k1.w;
                t0 += a2.x * k2.x + a2.y * k2.y + a2.z * k2.z + a2.w * k2.w;
                t0 += a3.x * k3.x + a3.y * k3.y + a3.z * k3.z + a3.w * k3.w;
                s[qq] += t0;
            }
        }

        int kidx = kt + lane;
#pragma unroll
        for (int qq = 0; qq < 4; qq++) {
            int qg = q0 + warp * 4 + qq;
            float sv = s[qq] * ATT_SCALE;
            bool valid = (kidx < Tk) && (!causal || kidx <= qg);
            if (!valid) sv = -1e30f;
            float mt = sv;
#pragma unroll
            for (int o = 16; o; o >>= 1) mt = fmaxf(mt, __shfl_xor_sync(0xffffffffu, mt, o));
            float mn = fmaxf(m[qq], mt);
            float p = __expf(sv - mn);
            float corr = __expf(m[qq] - mn);
            float ps = p;
#pragma unroll
            for (int o = 16; o; o >>= 1) ps += __shfl_xor_sync(0xffffffffu, ps, o);
            l[qq] = l[qq] * corr + ps;
            m[qq] = mn;
            acc[qq].x *= corr; acc[qq].y *= corr; acc[qq].z *= corr; acc[qq].w *= corr;
#pragma unroll
            for (int j = 0; j < 32; j++) {
                float pj = __shfl_sync(0xffffffffu, p, j);
                float4 v = *(const float4*)&Vs[j * 128 + lane * 4];
                acc[qq].x = fmaf(pj, v.x, acc[qq].x);
                acc[qq].y = fmaf(pj, v.y, acc[qq].y);
                acc[qq].z = fmaf(pj, v.z, acc[qq].z);
                acc[qq].w = fmaf(pj, v.w, acc[qq].w);
            }
        }
    }

    float gate = 1.f;
    if (gatep) gate = *gatep;
#pragma unroll
    for (int qq = 0; qq < 4; qq++) {
        int qg = q0 + warp * 4 + qq;
        if (qg >= Tq) continue;
        float sc = gate / l[qq];
        long off = qbase + (long)qg * 128 + lane * 4;
        float4 o;
        o.x = acc[qq].x * sc; o.y = acc[qq].y * sc; o.z = acc[qq].z * sc; o.w = acc[qq].w * sc;
        if (accum) {
            float4 prev = *(const float4*)&Out[off];
            o.x += prev.x; o.y += prev.y; o.z += prev.z; o.w += prev.w;
        }
        *(float4*)&Out[off] = o;
    }
}

// ---------------- host launcher ----------------
static float* sym(const void* symbol)
{
    void* p = nullptr;
    cudaGetSymbolAddress(&p, symbol);
    return (float*)p;
}

extern "C" void kernel_launch(void* const* d_in, const int* in_sizes, int n_in,
                              void* d_out, int out_size)
{
    (void)in_sizes; (void)n_in; (void)out_size;
    const float* x        = (const float*)d_in[0];
    const float* audio    = (const float*)d_in[1];
    const float* rope_cos = (const float*)d_in[2];
    const float* rope_sin = (const float*)d_in[3];
    // d_in[4] = mask (causal tril, implicit), d_in[5] = max_seq_length (unused)
    const float* pad_k    = (const float*)d_in[6];
    const float* pad_v    = (const float*)d_in[7];
    const float* c_attn_w = (const float*)d_in[8];
    const float* c_proj_w = (const float*)d_in[9];
    const float* adapter  = (const float*)d_in[10];
    const float* gating   = (const float*)d_in[11];   // scalar
    const float* rms_gate = (const float*)d_in[12];
    const float* rms_key  = (const float*)d_in[13];
    const float* rms_val  = (const float*)d_in[14];
    const float* proj_dn  = (const float*)d_in[15];
    const float* proj_up  = (const float*)d_in[16];
    const float* pq128    = (const float*)d_in[17];
    const float* pq32     = (const float*)d_in[18];
    const float* pgating  = (const float*)d_in[19];   // scalar
    const float* wkw      = (const float*)d_in[20];
    const float* wvw      = (const float*)d_in[21];
    const float* wvb      = (const float*)d_in[22];
    float* out = (float*)d_out;

    float *qkv = sym(g_qkv), *q = sym(g_q), *k = sym(g_k), *v = sym(g_v), *y = sym(g_y);
    float *pref = sym(g_pref), *aqkv = sym(g_aqkv), *ak = sym(g_ak), *av = sym(g_av);
    float *wkn = sym(g_wkn), *wvn = sym(g_wvn), *hid = sym(g_hid), *wk = sym(g_wk), *wv = sym(g_wv);
    float *pk = sym(g_pk), *pv = sym(g_pv), *q2a = sym(g_q2a), *q2 = sym(g_q2), *ybt = sym(g_ybt);

    const int M = BB * TT;            // 2048
    const int MA = BB * AT;           // 3000

    // 1) qkv = x @ c_attn_w
    sgemm_kernel<<<dim3((3*CC)/128, M/128), 256>>>(x, c_attn_w, qkv, M, 3*CC, CC, nullptr, 0);

    // 2) split + rope
    {
        int tot = BB * TT * NH * 64;
        split_rope_kernel<<<(tot + 255) / 256, 256>>>(qkv, rope_cos, rope_sin, q, k, v);
    }

    // 3) causal self-attention -> y
    attn_kernel<<<dim3(TT/32, NH, BB), 256>>>(q, k, v, y, NH, TT, TT,
                                              (long)NH*TT*HS, (long)TT*HS, 1, nullptr, 0);

    // 4) adapter branch
    rmsnorm_kernel<<<ALEN, 256>>>(adapter, rms_gate, pref, CC);
    sgemm_kernel<<<dim3((3*CC)/128, 1), 256>>>(pref, c_attn_w, aqkv, ALEN, 3*CC, CC, nullptr, 0);
    adapter_split_kernel<<<(NH*ALEN*HS + 255) / 256, 256>>>(aqkv, ak, av);
    attn_kernel<<<dim3(TT/32, NH, BB), 256>>>(q, ak, av, y, NH, TT, ALEN,
                                              0L, (long)ALEN*HS, 0, gating, 1);

    // 5) whisper key path
    sgemm_kernel<<<dim3(AD/128, (MA + 127)/128), 256>>>(audio, wkw, wkn, MA, AD, AD, nullptr, 0);
    rmsnorm_kernel<<<MA, 256>>>(wkn, rms_key, wkn, AD);
    sgemm_kernel<<<dim3(1, (MA + 127)/128), 256>>>(wkn, proj_dn, hid, MA, DHID, AD, nullptr, 1);
    sgemm_kernel<<<dim3(AD/128, (MA + 127)/128), 256>>>(hid, proj_up, wk, MA, AD, DHID, nullptr, 0);

    // 6) whisper value path
    sgemm_kernel<<<dim3(AD/128, (MA + 127)/128), 256>>>(audio, wvw, wvn, MA, AD, AD, wvb, 0);
    rmsnorm_kernel<<<MA, 256>>>(wvn, rms_val, wvn, AD);
    sgemm_kernel<<<dim3(1, (MA + 127)/128), 256>>>(wvn, proj_dn, hid, MA, DHID, AD, nullptr, 1);
    sgemm_kernel<<<dim3(AD/128, (MA + 127)/128), 256>>>(hid, proj_up, wv, MA, AD, DHID, nullptr, 0);

    // 7) assemble pk/pv
    {
        int tot = BB * NH * AT * HS;
        fill_pkv_kernel<<<(tot + 255) / 256, 256>>>(wk, pad_k, pk);
        fill_pkv_kernel<<<(tot + 255) / 256, 256>>>(wv, pad_v, pv);
    }

    // 8) q2 = (q @ proj_q128) head-mixed by proj_q32
    sgemm_kernel<<<dim3(1, (BB*NH*TT)/128), 256>>>(q, pq128, q2a, BB*NH*TT, HS, HS, nullptr, 0);
    headmix_kernel<<<BB * TT, 256>>>(q2a, pq32, q2);

    // 9) whisper cross-attention -> y += proj_gating * wy
    attn_kernel<<<dim3(TT/32, NH, BB), 256>>>(q2, pk, pv, y, NH, TT, AT,
                                              (long)NH*AT*HS, (long)AT*HS, 0, pgating, 1);

    // 10) transpose + output projection
    {
        int tot = BB * TT * CC;
        transpose_y_kernel<<<(tot + 255) / 256, 256>>>(y, ybt);
    }
    sgemm_kernel<<<dim3(CC/128, M/128), 256>>>(ybt, c_proj_w, out, M, CC, CC, nullptr, 0);
}

// round 3
// speedup vs baseline: 1.9227x; 1.9227x over previous
#include <cuda_runtime.h>
#include <cuda_bf16.h>
#include <math.h>
#include <stdint.h>

// ---------------- problem constants ----------------
#define BB 2
#define TT 1024
#define CC 4096
#define NH 32
#define HS 128
#define ALEN 10
#define AT 1500
#define AD 1280
#define NWH 20
#define WHD 64
#define DHID 80           // AD/16
#define ATT_SCALE 0.08838834764831845f   // 1/sqrt(128)

// ---------------- scratch buffers (device globals; no allocation) ----------------
__device__ float g_qkv [BB*TT*3*CC];
__device__ float g_q   [BB*NH*TT*HS];
__device__ float g_k   [BB*NH*TT*HS];
__device__ float g_v   [BB*NH*TT*HS];
__device__ float g_y   [BB*NH*TT*HS];
__device__ float g_pref[ALEN*CC];
__device__ float g_aqkv[ALEN*3*CC];
__device__ float g_ak  [NH*ALEN*HS];
__device__ float g_av  [NH*ALEN*HS];
__device__ float g_wkn [BB*AT*AD];
__device__ float g_wvn [BB*AT*AD];
__device__ float g_hid [BB*AT*DHID];
__device__ float g_wk  [BB*AT*AD];
__device__ float g_wv  [BB*AT*AD];
__device__ float g_pk  [BB*NH*AT*HS];
__device__ float g_pv  [BB*NH*AT*HS];
__device__ float g_q2a [BB*NH*TT*HS];
__device__ float g_q2  [BB*NH*TT*HS];
__device__ float g_ybt [BB*TT*CC];
// transposed weights [N, K] for B operand (row.col mma wants B as [N][K] contiguous-K)
__device__ float g_attn_wt[3*CC*CC];
__device__ float g_proj_wt[CC*CC];
__device__ float g_wkw_t [AD*AD];
__device__ float g_wvw_t [AD*AD];
__device__ float g_pdn_t [DHID*AD];
__device__ float g_pup_t [AD*DHID];
__device__ float g_pq128_t[HS*HS];

// ================= helpers =================
__device__ __forceinline__ uint32_t smem_u32(const void* p) {
    uint32_t a;
    asm("{ .reg .u64 t; cvta.to.shared.u64 t, %1; cvt.u32.u64 %0, t; }" : "=r"(a) : "l"(p));
    return a;
}

#define LDSM_X4(r, addr) \
    asm volatile("ldmatrix.sync.aligned.m8n8.x4.shared.b16 {%0,%1,%2,%3}, [%4];" \
        : "=r"((r)[0]), "=r"((r)[1]), "=r"((r)[2]), "=r"((r)[3]) : "r"(addr))
#define LDSM_X2(r, addr) \
    asm volatile("ldmatrix.sync.aligned.m8n8.x2.shared.b16 {%0,%1}, [%2];" \
        : "=r"((r)[0]), "=r"((r)[1]) : "r"(addr))
#define MMA_BF16(c, a, b) \
    asm volatile("mma.sync.aligned.m16n8k16.row.col.f32.bf16.bf16.f32 " \
        "{%0,%1,%2,%3}, {%4,%5,%6,%7}, {%8,%9}, {%0,%1,%2,%3};" \
        : "+f"((c)[0]), "+f"((c)[1]), "+f"((c)[2]), "+f"((c)[3]) \
        : "r"((a)[0]), "r"((a)[1]), "r"((a)[2]), "r"((a)[3]), "r"((b)[0]), "r"((b)[1]))

// split a float4 into bf16 hi plane (4 bf16 = uint2) and residual lo plane
__device__ __forceinline__ void cvt_split4(const float4 v, uint2& hi, uint2& lo) {
    __nv_bfloat16 h0 = __float2bfloat16(v.x), h1 = __float2bfloat16(v.y);
    __nv_bfloat16 h2 = __float2bfloat16(v.z), h3 = __float2bfloat16(v.w);
    float r0 = v.x - __bfloat162float(h0), r1 = v.y - __bfloat162float(h1);
    float r2 = v.z - __bfloat162float(h2), r3 = v.w - __bfloat162float(h3);
    __nv_bfloat162 p01, p23, q01, q23;
    p01.x = h0; p01.y = h1; p23.x = h2; p23.y = h3;
    q01.x = __float2bfloat16(r0); q01.y = __float2bfloat16(r1);
    q23.x = __float2bfloat16(r2); q23.y = __float2bfloat16(r3);
    hi.x = *(uint32_t*)&p01; hi.y = *(uint32_t*)&p23;
    lo.x = *(uint32_t*)&q01; lo.y = *(uint32_t*)&q23;
}

// ================= bf16-split tensor-core GEMM =================
// C[M,N] = A[M,K] @ W, Bt = W^T as [N,K] row-major.
// CTA tile 128x128, BK=32, double-buffered. SMEM row = 128B: hi plane (granules
// 0..3) | lo plane (granules 4..7), granule-XOR swizzle by (row&7).
#define GEMM_SMEM_BYTES 65536

__global__ __launch_bounds__(256, 1) void gemm_bf16s_kernel(
    const float* __restrict__ A, const float* __restrict__ Bt, float* __restrict__ C,
    int M, int N, int K, const float* __restrict__ bias, int act)
{
    extern __shared__ __align__(128) unsigned char smem[];
    const uint32_t sbase = smem_u32(smem);
    const int tid = threadIdx.x;
    const int lane = tid & 31, warp = tid >> 5;
    const int wm = warp & 1, wn = warp >> 1;           // 2 x 4 warp grid
    const int m0 = blockIdx.y * 128, n0 = blockIdx.x * 128;
    const int nkt = (K + 31) / 32;

    float acc[4][4][4];
#pragma unroll
    for (int i = 0; i < 4; i++)
#pragma unroll
        for (int j = 0; j < 4; j++)
#pragma unroll
            for (int e = 0; e < 4; e++) acc[i][j][e] = 0.f;

    float4 aReg[4], bReg[4];

    auto glob_load = [&](int kt) {
#pragma unroll
        for (int q = 0; q < 4; q++) {
            int idx = q * 256 + tid;
            int r = idx >> 3, c = idx & 7;
            int gk = kt * 32 + c * 4;
            float4 av = make_float4(0.f, 0.f, 0.f, 0.f);
            int gr = m0 + r;
            if (gr < M) {
                const float* p = A + (long)gr * K + gk;
                if (gk + 3 < K) av = *(const float4*)p;
                else {
                    if (gk + 0 < K) av.x = p[0];
                    if (gk + 1 < K) av.y = p[1];
                    if (gk + 2 < K) av.z = p[2];
                }
            }
            aReg[q] = av;
            float4 bv = make_float4(0.f, 0.f, 0.f, 0.f);
            int gn = n0 + r;
            if (gn < N) {
                const float* p = Bt + (long)gn * K + gk;
                if (gk + 3 < K) bv = *(const float4*)p;
                else {
                    if (gk + 0 < K) bv.x = p[0];
                    if (gk + 1 < K) bv.y = p[1];
                    if (gk + 2 < K) bv.z = p[2];
                }
            }
            bReg[q] = bv;
        }
    };

    auto smem_store = [&](int buf) {
        uint32_t aB = buf * 32768u;
        uint32_t bB = aB + 16384u;
#pragma unroll
        for (int q = 0; q < 4; q++) {
            int idx = q * 256 + tid;
            int r = idx >> 3, c = idx & 7;
            uint32_t sub = (uint32_t)(c & 1) * 8u;
            uint32_t gh = (uint32_t)((c >> 1) ^ (r & 7));
            uint32_t gl = (uint32_t)((4 + (c >> 1)) ^ (r & 7));
            uint2 hi, lo;
            cvt_split4(aReg[q], hi, lo);
            *(uint2*)(smem + aB + (uint32_t)r * 128u + gh * 16u + sub) = hi;
            *(uint2*)(smem + aB + (uint32_t)r * 128u + gl * 16u + sub) = lo;
            cvt_split4(bReg[q], hi, lo);
            *(uint2*)(smem + bB + (uint32_t)r * 128u + gh * 16u + sub) = hi;
            *(uint2*)(smem + bB + (uint32_t)r * 128u + gl * 16u + sub) = lo;
        }
    };

    auto compute = [&](int buf) {
        uint32_t aB = sbase + buf * 32768u;
        uint32_t bB = aB + 16384u;
#pragma unroll
        for (int ks = 0; ks < 2; ks++) {
            uint32_t kg = (uint32_t)ks * 2u;
            uint32_t ah[4][4], al[4][4], bh[4][2], bl[4][2];
#pragma unroll
            for (int i = 0; i < 4; i++) {
                uint32_t row = (uint32_t)(wm * 64 + i * 16 + (lane & 15));
                uint32_t gcol = kg + (uint32_t)(lane >> 4);
                uint32_t rb = aB + row * 128u;
                LDSM_X4(ah[i], rb + ((gcol ^ (row & 7u)) << 4));
                LDSM_X4(al[i], rb + (((gcol + 4u) ^ (row & 7u)) << 4));
            }
#pragma unroll
            for (int j = 0; j < 4; j++) {
                uint32_t row = (uint32_t)(wn * 32 + j * 8 + (lane & 7));
                uint32_t gcol = kg + (uint32_t)((lane >> 3) & 1);
                uint32_t rb = bB + row * 128u;
                LDSM_X2(bh[j], rb + ((gcol ^ (row & 7u)) << 4));
                LDSM_X2(bl[j], rb + (((gcol + 4u) ^ (row & 7u)) << 4));
            }
#pragma unroll
            for (int i = 0; i < 4; i++)
#pragma unroll
                for (int j = 0; j < 4; j++) {
                    MMA_BF16(acc[i][j], ah[i], bh[j]);
                    MMA_BF16(acc[i][j], ah[i], bl[j]);
                    MMA_BF16(acc[i][j], al[i], bh[j]);
                }
        }
    };

    glob_load(0);
    smem_store(0);
    __syncthreads();
    for (int kt = 0; kt < nkt; kt++) {
        int buf = kt & 1;
        if (kt + 1 < nkt) glob_load(kt + 1);
        compute(buf);
        __syncthreads();
        if (kt + 1 < nkt) {
            smem_store(buf ^ 1);
            __syncthreads();
        }
    }

    // epilogue
#pragma unroll
    for (int i = 0; i < 4; i++) {
#pragma unroll
        for (int j = 0; j < 4; j++) {
            int gc = n0 + wn * 32 + j * 8 + (lane & 3) * 2;
            float b0v = 0.f, b1v = 0.f;
            if (bias) {
                if (gc < N)     b0v = bias[gc];
                if (gc + 1 < N) b1v = bias[gc + 1];
            }
#pragma unroll
            for (int half = 0; half < 2; half++) {
                int gr = m0 + wm * 64 + i * 16 + (lane >> 2) + half * 8;
                if (gr >= M) continue;
                float v0 = acc[i][j][half * 2 + 0] + b0v;
                float v1 = acc[i][j][half * 2 + 1] + b1v;
                if (act == 1) {
                    v0 = v0 / (1.f + __expf(-v0));
                    v1 = v1 / (1.f + __expf(-v1));
                }
                if (gc + 1 < N) {
                    *(float2*)&C[(long)gr * N + gc] = make_float2(v0, v1);
                } else if (gc < N) {
                    C[(long)gr * N + gc] = v0;
                }
            }
        }
    }
}

// ================= transpose: in[R,C] -> out[C,R] =================
__global__ void transpose_kernel(const float* __restrict__ in, float* __restrict__ out, int R, int C)
{
    __shared__ float t[32][33];
    int bx = blockIdx.x * 32, by = blockIdx.y * 32;
    int x = bx + threadIdx.x;
#pragma unroll
    for (int j = 0; j < 32; j += 8) {
        int y = by + threadIdx.y + j;
        if (x < C && y < R) t[threadIdx.y + j][threadIdx.x] = in[(long)y * C + x];
    }
    __syncthreads();
    int x2 = by + threadIdx.x;
#pragma unroll
    for (int j = 0; j < 32; j += 8) {
        int y2 = bx + threadIdx.y + j;
        if (x2 < R && y2 < C) out[(long)y2 * R + x2] = t[threadIdx.x][threadIdx.y + j];
    }
}

// ================= rmsnorm per row =================
__global__ void rmsnorm_kernel(const float* __restrict__ in, const float* __restrict__ w,
                               float* __restrict__ out, int N)
{
    int row = blockIdx.x;
    const float* x = in + (long)row * N;
    float ss = 0.f;
    for (int c = threadIdx.x; c < N; c += 256) { float v = x[c]; ss = fmaf(v, v, ss); }
    __shared__ float sh[32];
    int lane = threadIdx.x & 31, wid = threadIdx.x >> 5;
#pragma unroll
    for (int o = 16; o; o >>= 1) ss += __shfl_xor_sync(0xffffffffu, ss, o);
    if (lane == 0) sh[wid] = ss;
    __syncthreads();
    float tot = (threadIdx.x < 8) ? sh[threadIdx.x] : 0.f;
    if (wid == 0) {
#pragma unroll
        for (int o = 16; o; o >>= 1) tot += __shfl_xor_sync(0xffffffffu, tot, o);
    }
    __shared__ float ssc;
    if (threadIdx.x == 0) ssc = rsqrtf(tot / (float)N + 1e-5f);
    __syncthreads();
    float sc = ssc;
    float* o = out + (long)row * N;
    for (int c = threadIdx.x; c < N; c += 256) o[c] = x[c] * sc * w[c];
}

// ================= split qkv + rope =================
__global__ void split_rope_kernel(const float* __restrict__ qkv,
                                  const float* __restrict__ cos_, const float* __restrict__ sin_,
                                  float* __restrict__ q, float* __restrict__ k, float* __restrict__ v)
{
    int idx = blockIdx.x * blockDim.x + threadIdx.x;
    if (idx >= BB * TT * NH * 64) return;
    int i = idx & 63;
    int h = (idx >> 6) & 31;
    int t = (idx >> 11) & 1023;
    int b = idx >> 21;
    long base = ((long)(b * TT + t)) * (3 * CC) + h * HS + 2 * i;
    float q0 = qkv[base],        q1 = qkv[base + 1];
    float k0 = qkv[base + CC],   k1 = qkv[base + CC + 1];
    float v0 = qkv[base + 2*CC], v1 = qkv[base + 2*CC + 1];
    float c = cos_[t * 64 + i], s = sin_[t * 64 + i];
    long ob = ((long)((b * NH + h) * TT + t)) * HS + 2 * i;
    q[ob] = q0 * c - q1 * s;  q[ob + 1] = q1 * c + q0 * s;
    k[ob] = k0 * c - k1 * s;  k[ob + 1] = k1 * c + k0 * s;
    v[ob] = v0;               v[ob + 1] = v1;
}

// ================= adapter split =================
__global__ void adapter_split_kernel(const float* __restrict__ aqkv,
                                     float* __restrict__ ak, float* __restrict__ av)
{
    int idx = blockIdx.x * blockDim.x + threadIdx.x;
    if (idx >= NH * ALEN * HS) return;
    int d = idx & 127;
    int a = (idx >> 7) % ALEN;
    int h = idx / (ALEN * HS);
    ak[idx] = aqkv[(long)a * (3 * CC) + CC     + h * HS + d];
    av[idx] = aqkv[(long)a * (3 * CC) + 2 * CC + h * HS + d];
}

// ================= assemble pk/pv =================
__global__ void fill_pkv_kernel(const float* __restrict__ wflat, const float* __restrict__ pad,
                                float* __restrict__ pkv)
{
    int idx = blockIdx.x * blockDim.x + threadIdx.x;
    if (idx >= BB * NH * AT * HS) return;
    int d = idx & 127;
    int t = (idx >> 7) % AT;
    int h = (idx / (HS * AT)) & 31;
    int b = idx / (HS * AT * NH);
    float v;
    if (h < NWH && d < WHD)
        v = wflat[(long)b * (AT * AD) + h * (AT * WHD) + t * WHD + d];
    else
        v = pad[((long)b * AT + t) * HS + d];
    pkv[idx] = v;
}

// ================= head mix =================
__global__ __launch_bounds__(256) void headmix_kernel(const float* __restrict__ q2a,
                                                      const float* __restrict__ w,
                                                      float* __restrict__ q2)
{
    int bt = blockIdx.x;
    int b = bt >> 10, t = bt & 1023;
    __shared__ float sm[NH * HS];
    __shared__ float ws[NH * NH];
    for (int i = threadIdx.x; i < NH * HS; i += 256) {
        int h = i >> 7, d = i & 127;
        sm[i] = q2a[(((long)(b * NH + h)) * TT + t) * HS + d];
    }
    for (int i = threadIdx.x; i < NH * NH; i += 256) ws[i] = w[i];
    __syncthreads();
    for (int i = threadIdx.x; i < NH * HS; i += 256) {
        int g = i >> 7, d = i & 127;
        float acc = 0.f;
#pragma unroll
        for (int h = 0; h < NH; h++) acc = fmaf(sm[h * HS + d], ws[h * NH + g], acc);
        q2[(((long)(b * NH + g)) * TT + t) * HS + d] = acc;
    }
}

// ================= [B,NH,T,HS] -> [B,T,C] =================
__global__ void transpose_y_kernel(const float* __restrict__ y, float* __restrict__ out)
{
    int idx = blockIdx.x * blockDim.x + threadIdx.x;
    if (idx >= BB * TT * CC) return;
    int d = idx & 127;
    int h = (idx >> 7) & 31;
    int t = (idx >> 12) & 1023;
    int b = idx >> 22;
    out[idx] = y[(((long)(b * NH + h)) * TT + t) * HS + d];
}

// ================= flash-style attention (fp32 SIMT) =================
__global__ __launch_bounds__(256) void attn_kernel(
    const float* __restrict__ Q, const float* __restrict__ K, const float* __restrict__ V,
    float* __restrict__ Out, int H, int Tq, int Tk,
    long kvbs, long kvhs, int causal, const float* __restrict__ gatep, int accum)
{
    __shared__ float Qs[32 * 128];
    __shared__ float Ks[32 * 128];
    __shared__ float Vs[32 * 128];
    const int qt = blockIdx.x, h = blockIdx.y, b = blockIdx.z;
    const int tid = threadIdx.x, warp = tid >> 5, lane = tid & 31;
    const int q0 = qt * 32;
    const long qbase = ((long)(b * H + h)) * Tq * 128;

    for (int i = tid; i < 32 * 32; i += 256) {
        int r = i >> 5, c4 = i & 31;
        float4 val = make_float4(0.f, 0.f, 0.f, 0.f);
        if (q0 + r < Tq)
            val = *(const float4*)&Q[qbase + (long)(q0 + r) * 128 + c4 * 4];
        *(float4*)&Qs[r * 128 + c4 * 4] = val;
    }

    float m[4], l[4];
    float4 acc[4];
#pragma unroll
    for (int qq = 0; qq < 4; qq++) { m[qq] = -1e30f; l[qq] = 0.f; acc[qq] = make_float4(0,0,0,0); }

    const long kbase = (long)b * kvbs + (long)h * kvhs;
    const int kend = causal ? min(Tk, q0 + 32) : Tk;

    for (int kt = 0; kt < kend; kt += 32) {
        __syncthreads();
        for (int i = tid; i < 32 * 32; i += 256) {
            int r = i >> 5, c4 = i & 31;
            float4 kv = make_float4(0,0,0,0), vv = make_float4(0,0,0,0);
            if (kt + r < Tk) {
                long off = kbase + (long)(kt + r) * 128 + c4 * 4;
                kv = *(const float4*)&K[off];
                vv = *(const float4*)&V[off];
            }
            *(float4*)&Ks[r * 128 + ((c4 ^ r) & 31) * 4] = kv;
            *(float4*)&Vs[r * 128 + c4 * 4] = vv;
        }
        __syncthreads();

        float s[4] = {0.f, 0.f, 0.f, 0.f};
#pragma unroll
        for (int c = 0; c < 32; c += 4) {
            float4 k0v = *(const float4*)&Ks[lane * 128 + (((c + 0) ^ lane) & 31) * 4];
            float4 k1v = *(const float4*)&Ks[lane * 128 + (((c + 1) ^ lane) & 31) * 4];
            float4 k2v = *(const float4*)&Ks[lane * 128 + (((c + 2) ^ lane) & 31) * 4];
            float4 k3v = *(const float4*)&Ks[lane * 128 + (((c + 3) ^ lane) & 31) * 4];
#pragma unroll
            for (int qq = 0; qq < 4; qq++) {
                const float* qr = &Qs[(warp * 4 + qq) * 128 + c * 4];
                float4 a0 = *(const float4*)&qr[0];
                float4 a1 = *(const float4*)&qr[4];
                float4 a2 = *(const float4*)&qr[8];
                float4 a3 = *(const float4*)&qr[12];
                float t0;
                t0  = a0.x * k0v.x + a0.y * k0v.y + a0.z * k0v.z + a0.w * k0v.w;
                t0 += a1.x * k1v.x + a1.y * k1v.y + a1.z * k1v.z + a1.w * k1v.w;
                t0 += a2.x * k2v.x + a2.y * k2v.y + a2.z * k2v.z + a2.w * k2v.w;
                t0 += a3.x * k3v.x + a3.y * k3v.y + a3.z * k3v.z + a3.w * k3v.w;
                s[qq] += t0;
            }
        }

        int kidx = kt + lane;
#pragma unroll
        for (int qq = 0; qq < 4; qq++) {
            int qg = q0 + warp * 4 + qq;
            float sv = s[qq] * ATT_SCALE;
            bool valid = (kidx < Tk) && (!causal || kidx <= qg);
            if (!valid) sv = -1e30f;
            float mt = sv;
#pragma unroll
            for (int o = 16; o; o >>= 1) mt = fmaxf(mt, __shfl_xor_sync(0xffffffffu, mt, o));
            float mn = fmaxf(m[qq], mt);
            float p = __expf(sv - mn);
            float corr = __expf(m[qq] - mn);
            float ps = p;
#pragma unroll
            for (int o = 16; o; o >>= 1) ps += __shfl_xor_sync(0xffffffffu, ps, o);
            l[qq] = l[qq] * corr + ps;
            m[qq] = mn;
            acc[qq].x *= corr; acc[qq].y *= corr; acc[qq].z *= corr; acc[qq].w *= corr;
#pragma unroll
            for (int j = 0; j < 32; j++) {
                float pj = __shfl_sync(0xffffffffu, p, j);
                float4 v = *(const float4*)&Vs[j * 128 + lane * 4];
                acc[qq].x = fmaf(pj, v.x, acc[qq].x);
                acc[qq].y = fmaf(pj, v.y, acc[qq].y);
                acc[qq].z = fmaf(pj, v.z, acc[qq].z);
                acc[qq].w = fmaf(pj, v.w, acc[qq].w);
            }
        }
    }

    float gate = 1.f;
    if (gatep) gate = *gatep;
#pragma unroll
    for (int qq = 0; qq < 4; qq++) {
        int qg = q0 + warp * 4 + qq;
        if (qg >= Tq) continue;
        float sc = gate / l[qq];
        long off = qbase + (long)qg * 128 + lane * 4;
        float4 o;
        o.x = acc[qq].x * sc; o.y = acc[qq].y * sc; o.z = acc[qq].z * sc; o.w = acc[qq].w * sc;
        if (accum) {
            float4 prev = *(const float4*)&Out[off];
            o.x += prev.x; o.y += prev.y; o.z += prev.z; o.w += prev.w;
        }
        *(float4*)&Out[off] = o;
    }
}

// ================= host launcher =================
static float* symp(const void* symbol)
{
    void* p = nullptr;
    cudaGetSymbolAddress(&p, symbol);
    return (float*)p;
}

static inline void gemm_tc(const float* A, const float* Bt, float* C,
                           int M, int N, int K, const float* bias, int act)
{
    dim3 grid((N + 127) / 128, (M + 127) / 128);
    gemm_bf16s_kernel<<<grid, 256, GEMM_SMEM_BYTES>>>(A, Bt, C, M, N, K, bias, act);
}

extern "C" void kernel_launch(void* const* d_in, const int* in_sizes, int n_in,
                              void* d_out, int out_size)
{
    (void)in_sizes; (void)n_in; (void)out_size;
    const float* x        = (const float*)d_in[0];
    const float* audio    = (const float*)d_in[1];
    const float* rope_cos = (const float*)d_in[2];
    const float* rope_sin = (const float*)d_in[3];
    const float* pad_k    = (const float*)d_in[6];
    const float* pad_v    = (const float*)d_in[7];
    const float* c_attn_w = (const float*)d_in[8];
    const float* c_proj_w = (const float*)d_in[9];
    const float* adapter  = (const float*)d_in[10];
    const float* gating   = (const float*)d_in[11];
    const float* rms_gate = (const float*)d_in[12];
    const float* rms_key  = (const float*)d_in[13];
    const float* rms_val  = (const float*)d_in[14];
    const float* proj_dn  = (const float*)d_in[15];
    const float* proj_up  = (const float*)d_in[16];
    const float* pq128    = (const float*)d_in[17];
    const float* pq32     = (const float*)d_in[18];
    const float* pgating  = (const float*)d_in[19];
    const float* wkw      = (const float*)d_in[20];
    const float* wvw      = (const float*)d_in[21];
    const float* wvb      = (const float*)d_in[22];
    float* out = (float*)d_out;

    float *qkv = symp(g_qkv), *q = symp(g_q), *k = symp(g_k), *v = symp(g_v), *y = symp(g_y);
    float *pref = symp(g_pref), *aqkv = symp(g_aqkv), *ak = symp(g_ak), *av = symp(g_av);
    float *wkn = symp(g_wkn), *wvn = symp(g_wvn), *hid = symp(g_hid), *wk = symp(g_wk), *wv = symp(g_wv);
    float *pk = symp(g_pk), *pv = symp(g_pv), *q2a = symp(g_q2a), *q2 = symp(g_q2), *ybt = symp(g_ybt);
    float *attn_wt = symp(g_attn_wt), *proj_wt = symp(g_proj_wt);
    float *wkw_t = symp(g_wkw_t), *wvw_t = symp(g_wvw_t);
    float *pdn_t = symp(g_pdn_t), *pup_t = symp(g_pup_t), *pq128_t = symp(g_pq128_t);

    cudaFuncSetAttribute(gemm_bf16s_kernel, cudaFuncAttributeMaxDynamicSharedMemorySize,
                         GEMM_SMEM_BYTES);

    const int M = BB * TT;            // 2048
    const int MA = BB * AT;           // 3000
    dim3 tb(32, 8);

    // 0) weight transposes (W[K,N] -> Wt[N,K])
    transpose_kernel<<<dim3((3*CC + 31)/32, (CC + 31)/32), tb>>>(c_attn_w, attn_wt, CC, 3*CC);
    transpose_kernel<<<dim3((CC + 31)/32, (CC + 31)/32), tb>>>(c_proj_w, proj_wt, CC, CC);
    transpose_kernel<<<dim3((AD + 31)/32, (AD + 31)/32), tb>>>(wkw, wkw_t, AD, AD);
    transpose_kernel<<<dim3((AD + 31)/32, (AD + 31)/32), tb>>>(wvw, wvw_t, AD, AD);
    transpose_kernel<<<dim3((DHID + 31)/32, (AD + 31)/32), tb>>>(proj_dn, pdn_t, AD, DHID);
    transpose_kernel<<<dim3((AD + 31)/32, (DHID + 31)/32), tb>>>(proj_up, pup_t, DHID, AD);
    transpose_kernel<<<dim3((HS + 31)/32, (HS + 31)/32), tb>>>(pq128, pq128_t, HS, HS);

    // 1) qkv = x @ c_attn_w
    gemm_tc(x, attn_wt, qkv, M, 3*CC, CC, nullptr, 0);

    // 2) split + rope
    {
        int tot = BB * TT * NH * 64;
        split_rope_kernel<<<(tot + 255) / 256, 256>>>(qkv, rope_cos, rope_sin, q, k, v);
    }

    // 3) causal self-attention -> y
    attn_kernel<<<dim3(TT/32, NH, BB), 256>>>(q, k, v, y, NH, TT, TT,
                                              (long)NH*TT*HS, (long)TT*HS, 1, nullptr, 0);

    // 4) adapter branch
    rmsnorm_kernel<<<ALEN, 256>>>(adapter, rms_gate, pref, CC);
    gemm_tc(pref, attn_wt, aqkv, ALEN, 3*CC, CC, nullptr, 0);
    adapter_split_kernel<<<(NH*ALEN*HS + 255) / 256, 256>>>(aqkv, ak, av);
    attn_kernel<<<dim3(TT/32, NH, BB), 256>>>(q, ak, av, y, NH, TT, ALEN,
                                              0L, (long)ALEN*HS, 0, gating, 1);

    // 5) whisper key path
    gemm_tc(audio, wkw_t, wkn, MA, AD, AD, nullptr, 0);
    rmsnorm_kernel<<<MA, 256>>>(wkn, rms_key, wkn, AD);
    gemm_tc(wkn, pdn_t, hid, MA, DHID, AD, nullptr, 1);
    gemm_tc(hid, pup_t, wk, MA, AD, DHID, nullptr, 0);

    // 6) whisper value path
    gemm_tc(audio, wvw_t, wvn, MA, AD, AD, wvb, 0);
    rmsnorm_kernel<<<MA, 256>>>(wvn, rms_val, wvn, AD);
    gemm_tc(wvn, pdn_t, hid, MA, DHID, AD, nullptr, 1);
    gemm_tc(hid, pup_t, wv, MA, AD, DHID, nullptr, 0);

    // 7) assemble pk/pv
    {
        int tot = BB * NH * AT * HS;
        fill_pkv_kernel<<<(tot + 255) / 256, 256>>>(wk, pad_k, pk);
        fill_pkv_kernel<<<(tot + 255) / 256, 256>>>(wv, pad_v, pv);
    }

    // 8) q2 = (q @ proj_q128) head-mixed by proj_q32
    gemm_tc(q, pq128_t, q2a, BB*NH*TT, HS, HS, nullptr, 0);
    headmix_kernel<<<BB * TT, 256>>>(q2a, pq32, q2);

    // 9) whisper cross-attention -> y += proj_gating * wy
    attn_kernel<<<dim3(TT/32, NH, BB), 256>>>(q2, pk, pv, y, NH, TT, AT,
                                              (long)NH*AT*HS, (long)AT*HS, 0, pgating, 1);

    // 10) transpose + output projection
    {
        int tot = BB * TT * CC;
        transpose_y_kernel<<<(tot + 255) / 256, 256>>>(y, ybt);
    }
    gemm_tc(ybt, proj_wt, out, M, CC, CC, nullptr, 0);
}

// round 4
// speedup vs baseline: 2.8586x; 1.4868x over previous
#include <cuda_runtime.h>
#include <cuda_bf16.h>
#include <math.h>
#include <stdint.h>

// ---------------- problem constants ----------------
#define BB 2
#define TT 1024
#define CC 4096
#define NH 32
#define HS 128
#define ALEN 10
#define AT 1500
#define AD 1280
#define NWH 20
#define WHD 64
#define DHID 80           // AD/16
#define ATT_SCALE 0.08838834764831845f   // 1/sqrt(128)

// ---------------- scratch buffers (device globals; no allocation) ----------------
__device__ float g_qkv [BB*TT*3*CC];
__device__ float g_q   [BB*NH*TT*HS];
__device__ float g_k   [BB*NH*TT*HS];
__device__ float g_v   [BB*NH*TT*HS];
__device__ float g_y   [BB*NH*TT*HS];
__device__ float g_pref[ALEN*CC];
__device__ float g_aqkv[ALEN*3*CC];
__device__ float g_ak  [NH*ALEN*HS];
__device__ float g_av  [NH*ALEN*HS];
__device__ float g_wkn [BB*AT*AD];
__device__ float g_wvn [BB*AT*AD];
__device__ float g_hid [BB*AT*DHID];
__device__ float g_wk  [BB*AT*AD];
__device__ float g_wv  [BB*AT*AD];
__device__ float g_pk  [BB*NH*AT*HS];
__device__ float g_pv  [BB*NH*AT*HS];
__device__ float g_q2a [BB*NH*TT*HS];
__device__ float g_q2  [BB*NH*TT*HS];
__device__ float g_ybt [BB*TT*CC];
__device__ float g_attn_wt[3*CC*CC];
__device__ float g_proj_wt[CC*CC];
__device__ float g_wkw_t [AD*AD];
__device__ float g_wvw_t [AD*AD];
__device__ float g_pdn_t [DHID*AD];
__device__ float g_pup_t [AD*DHID];
__device__ float g_pq128_t[HS*HS];

// ================= helpers =================
__device__ __forceinline__ uint32_t smem_u32(const void* p) {
    uint32_t a;
    asm("{ .reg .u64 t; cvta.to.shared.u64 t, %1; cvt.u32.u64 %0, t; }" : "=r"(a) : "l"(p));
    return a;
}

#define LDSM_X4(r, addr) \
    asm volatile("ldmatrix.sync.aligned.m8n8.x4.shared.b16 {%0,%1,%2,%3}, [%4];" \
        : "=r"((r)[0]), "=r"((r)[1]), "=r"((r)[2]), "=r"((r)[3]) : "r"(addr))
#define LDSM_X4_T(r, addr) \
    asm volatile("ldmatrix.sync.aligned.m8n8.x4.trans.shared.b16 {%0,%1,%2,%3}, [%4];" \
        : "=r"((r)[0]), "=r"((r)[1]), "=r"((r)[2]), "=r"((r)[3]) : "r"(addr))
#define LDSM_X2(r, addr) \
    asm volatile("ldmatrix.sync.aligned.m8n8.x2.shared.b16 {%0,%1}, [%2];" \
        : "=r"((r)[0]), "=r"((r)[1]) : "r"(addr))
#define MMA_BF16(c, a, b) \
    asm volatile("mma.sync.aligned.m16n8k16.row.col.f32.bf16.bf16.f32 " \
        "{%0,%1,%2,%3}, {%4,%5,%6,%7}, {%8,%9}, {%0,%1,%2,%3};" \
        : "+f"((c)[0]), "+f"((c)[1]), "+f"((c)[2]), "+f"((c)[3]) \
        : "r"((a)[0]), "r"((a)[1]), "r"((a)[2]), "r"((a)[3]), "r"((b)[0]), "r"((b)[1]))

// split a float4 into bf16 hi plane (4 bf16 = uint2) and residual lo plane
__device__ __forceinline__ void cvt_split4(const float4 v, uint2& hi, uint2& lo) {
    __nv_bfloat16 h0 = __float2bfloat16(v.x), h1 = __float2bfloat16(v.y);
    __nv_bfloat16 h2 = __float2bfloat16(v.z), h3 = __float2bfloat16(v.w);
    float r0 = v.x - __bfloat162float(h0), r1 = v.y - __bfloat162float(h1);
    float r2 = v.z - __bfloat162float(h2), r3 = v.w - __bfloat162float(h3);
    __nv_bfloat162 p01, p23, q01, q23;
    p01.x = h0; p01.y = h1; p23.x = h2; p23.y = h3;
    q01.x = __float2bfloat16(r0); q01.y = __float2bfloat16(r1);
    q23.x = __float2bfloat16(r2); q23.y = __float2bfloat16(r3);
    hi.x = *(uint32_t*)&p01; hi.y = *(uint32_t*)&p23;
    lo.x = *(uint32_t*)&q01; lo.y = *(uint32_t*)&q23;
}
__device__ __forceinline__ void split2(float a, float b, uint32_t& hi, uint32_t& lo) {
    __nv_bfloat162 h;
    h.x = __float2bfloat16(a); h.y = __float2bfloat16(b);
    float ra = a - __bfloat162float(h.x);
    float rb = b - __bfloat162float(h.y);
    __nv_bfloat162 l;
    l.x = __float2bfloat16(ra); l.y = __float2bfloat16(rb);
    hi = *(uint32_t*)&h; lo = *(uint32_t*)&l;
}

// ================= bf16-split tensor-core GEMM (unchanged from R2) =================
#define GEMM_SMEM_BYTES 65536

__global__ __launch_bounds__(256, 1) void gemm_bf16s_kernel(
    const float* __restrict__ A, const float* __restrict__ Bt, float* __restrict__ C,
    int M, int N, int K, const float* __restrict__ bias, int act)
{
    extern __shared__ __align__(128) unsigned char smem[];
    const uint32_t sbase = smem_u32(smem);
    const int tid = threadIdx.x;
    const int lane = tid & 31, warp = tid >> 5;
    const int wm = warp & 1, wn = warp >> 1;
    const int m0 = blockIdx.y * 128, n0 = blockIdx.x * 128;
    const int nkt = (K + 31) / 32;

    float acc[4][4][4];
#pragma unroll
    for (int i = 0; i < 4; i++)
#pragma unroll
        for (int j = 0; j < 4; j++)
#pragma unroll
            for (int e = 0; e < 4; e++) acc[i][j][e] = 0.f;

    float4 aReg[4], bReg[4];

    auto glob_load = [&](int kt) {
#pragma unroll
        for (int q = 0; q < 4; q++) {
            int idx = q * 256 + tid;
            int r = idx >> 3, c = idx & 7;
            int gk = kt * 32 + c * 4;
            float4 av = make_float4(0.f, 0.f, 0.f, 0.f);
            int gr = m0 + r;
            if (gr < M) {
                const float* p = A + (long)gr * K + gk;
                if (gk + 3 < K) av = *(const float4*)p;
                else {
                    if (gk + 0 < K) av.x = p[0];
                    if (gk + 1 < K) av.y = p[1];
                    if (gk + 2 < K) av.z = p[2];
                }
            }
            aReg[q] = av;
            float4 bv = make_float4(0.f, 0.f, 0.f, 0.f);
            int gn = n0 + r;
            if (gn < N) {
                const float* p = Bt + (long)gn * K + gk;
                if (gk + 3 < K) bv = *(const float4*)p;
                else {
                    if (gk + 0 < K) bv.x = p[0];
                    if (gk + 1 < K) bv.y = p[1];
                    if (gk + 2 < K) bv.z = p[2];
                }
            }
            bReg[q] = bv;
        }
    };

    auto smem_store = [&](int buf) {
        uint32_t aB = buf * 32768u;
        uint32_t bB = aB + 16384u;
#pragma unroll
        for (int q = 0; q < 4; q++) {
            int idx = q * 256 + tid;
            int r = idx >> 3, c = idx & 7;
            uint32_t sub = (uint32_t)(c & 1) * 8u;
            uint32_t gh = (uint32_t)((c >> 1) ^ (r & 7));
            uint32_t gl = (uint32_t)((4 + (c >> 1)) ^ (r & 7));
            uint2 hi, lo;
            cvt_split4(aReg[q], hi, lo);
            *(uint2*)(smem + aB + (uint32_t)r * 128u + gh * 16u + sub) = hi;
            *(uint2*)(smem + aB + (uint32_t)r * 128u + gl * 16u + sub) = lo;
            cvt_split4(bReg[q], hi, lo);
            *(uint2*)(smem + bB + (uint32_t)r * 128u + gh * 16u + sub) = hi;
            *(uint2*)(smem + bB + (uint32_t)r * 128u + gl * 16u + sub) = lo;
        }
    };

    auto compute = [&](int buf) {
        uint32_t aB = sbase + buf * 32768u;
        uint32_t bB = aB + 16384u;
#pragma unroll
        for (int ks = 0; ks < 2; ks++) {
            uint32_t kg = (uint32_t)ks * 2u;
            uint32_t ah[4][4], al[4][4], bh[4][2], bl[4][2];
#pragma unroll
            for (int i = 0; i < 4; i++) {
                uint32_t row = (uint32_t)(wm * 64 + i * 16 + (lane & 15));
                uint32_t gcol = kg + (uint32_t)(lane >> 4);
                uint32_t rb = aB + row * 128u;
                LDSM_X4(ah[i], rb + ((gcol ^ (row & 7u)) << 4));
                LDSM_X4(al[i], rb + (((gcol + 4u) ^ (row & 7u)) << 4));
            }
#pragma unroll
            for (int j = 0; j < 4; j++) {
                uint32_t row = (uint32_t)(wn * 32 + j * 8 + (lane & 7));
                uint32_t gcol = kg + (uint32_t)((lane >> 3) & 1);
                uint32_t rb = bB + row * 128u;
                LDSM_X2(bh[j], rb + ((gcol ^ (row & 7u)) << 4));
                LDSM_X2(bl[j], rb + (((gcol + 4u) ^ (row & 7u)) << 4));
            }
#pragma unroll
            for (int i = 0; i < 4; i++)
#pragma unroll
                for (int j = 0; j < 4; j++) {
                    MMA_BF16(acc[i][j], ah[i], bh[j]);
                    MMA_BF16(acc[i][j], ah[i], bl[j]);
                    MMA_BF16(acc[i][j], al[i], bh[j]);
                }
        }
    };

    glob_load(0);
    smem_store(0);
    __syncthreads();
    for (int kt = 0; kt < nkt; kt++) {
        int buf = kt & 1;
        if (kt + 1 < nkt) glob_load(kt + 1);
        compute(buf);
        __syncthreads();
        if (kt + 1 < nkt) {
            smem_store(buf ^ 1);
            __syncthreads();
        }
    }

#pragma unroll
    for (int i = 0; i < 4; i++) {
#pragma unroll
        for (int j = 0; j < 4; j++) {
            int gc = n0 + wn * 32 + j * 8 + (lane & 3) * 2;
            float b0v = 0.f, b1v = 0.f;
            if (bias) {
                if (gc < N)     b0v = bias[gc];
                if (gc + 1 < N) b1v = bias[gc + 1];
            }
#pragma unroll
            for (int half = 0; half < 2; half++) {
                int gr = m0 + wm * 64 + i * 16 + (lane >> 2) + half * 8;
                if (gr >= M) continue;
                float v0 = acc[i][j][half * 2 + 0] + b0v;
                float v1 = acc[i][j][half * 2 + 1] + b1v;
                if (act == 1) {
                    v0 = v0 / (1.f + __expf(-v0));
                    v1 = v1 / (1.f + __expf(-v1));
                }
                if (gc + 1 < N) {
                    *(float2*)&C[(long)gr * N + gc] = make_float2(v0, v1);
                } else if (gc < N) {
                    C[(long)gr * N + gc] = v0;
                }
            }
        }
    }
}

// ================= tensor-core flash attention =================
// Block: 128 threads / 4 warps, 64 queries (warp w: rows w*16..w*16+15),
// 64-key tiles. K/V in SMEM as bf16 hi/lo planes (16KB each): Kh 0, Kl 16K,
// Vh 32K, Vl 48K. Rows 256B, 16B granules XOR-swizzled by (row&7).
#define ATTN_SMEM_BYTES 65536

__global__ __launch_bounds__(128, 1) void attn_mma_kernel(
    const float* __restrict__ Q, const float* __restrict__ K, const float* __restrict__ V,
    float* __restrict__ Out, int H, int Tq, int Tk,
    long kvbs, long kvhs, int causal, const float* __restrict__ gatep, int accum)
{
    extern __shared__ __align__(128) unsigned char smem[];
    const uint32_t sb = smem_u32(smem);
    const int tid = threadIdx.x, lane = tid & 31, warp = tid >> 5;
    const int q0 = blockIdx.x * 64, h = blockIdx.y, b = blockIdx.z;
    const long qbase = ((long)(b * H + h)) * Tq * 128;
    const long kbase = (long)b * kvbs + (long)h * kvhs;
    const int qw = q0 + warp * 16;
    const int r0 = lane >> 2;
    const int c2 = (lane & 3) * 2;
    const uint32_t ln7 = lane & 7u;

    // Q fragments, pre-scaled, hi/lo split. qh[kc][4], ql[kc][4]
    uint32_t qh[8][4], ql[8][4];
    {
        const float* qp0 = Q + qbase + (long)(qw + r0) * 128;
        const float* qp1 = qp0 + 8 * 128;
#pragma unroll
        for (int kc = 0; kc < 8; kc++) {
            float2 x0 = *(const float2*)&qp0[kc * 16 + c2];
            float2 x1 = *(const float2*)&qp1[kc * 16 + c2];
            float2 x2 = *(const float2*)&qp0[kc * 16 + c2 + 8];
            float2 x3 = *(const float2*)&qp1[kc * 16 + c2 + 8];
            split2(x0.x * ATT_SCALE, x0.y * ATT_SCALE, qh[kc][0], ql[kc][0]);
            split2(x1.x * ATT_SCALE, x1.y * ATT_SCALE, qh[kc][1], ql[kc][1]);
            split2(x2.x * ATT_SCALE, x2.y * ATT_SCALE, qh[kc][2], ql[kc][2]);
            split2(x3.x * ATT_SCALE, x3.y * ATT_SCALE, qh[kc][3], ql[kc][3]);
        }
    }

    float o[16][4];
#pragma unroll
    for (int n = 0; n < 16; n++)
#pragma unroll
        for (int e = 0; e < 4; e++) o[n][e] = 0.f;
    float m0v = -1e30f, m1v = -1e30f, l0v = 0.f, l1v = 0.f;

    const int kend = causal ? min(Tk, q0 + 64) : Tk;

    for (int kt = 0; kt < kend; kt += 64) {
        __syncthreads();
        // load + convert K/V tile
#pragma unroll
        for (int it = 0; it < 16; it++) {
            int idx = it * 128 + tid;
            int r = idx >> 5, c4 = idx & 31;
            float4 kvv = make_float4(0.f, 0.f, 0.f, 0.f);
            float4 vvv = make_float4(0.f, 0.f, 0.f, 0.f);
            if (kt + r < Tk) {
                long off = kbase + (long)(kt + r) * 128 + c4 * 4;
                kvv = *(const float4*)&K[off];
                vvv = *(const float4*)&V[off];
            }
            uint32_t g = (uint32_t)(c4 >> 1), sub = (uint32_t)(c4 & 1) * 8u;
            uint32_t gs = (g & 8u) | ((g & 7u) ^ ((uint32_t)r & 7u));
            uint32_t ro = (uint32_t)r * 256u + gs * 16u + sub;
            uint2 hi, lo;
            cvt_split4(kvv, hi, lo);
            *(uint2*)(smem + ro)          = hi;
            *(uint2*)(smem + 16384u + ro) = lo;
            cvt_split4(vvv, hi, lo);
            *(uint2*)(smem + 32768u + ro) = hi;
            *(uint2*)(smem + 49152u + ro) = lo;
        }
        __syncthreads();

        // ---- S = Q K^T ----
        float s[8][4];
#pragma unroll
        for (int n = 0; n < 8; n++)
#pragma unroll
            for (int e = 0; e < 4; e++) s[n][e] = 0.f;

#pragma unroll
        for (int kc2 = 0; kc2 < 4; kc2++) {
#pragma unroll
            for (int nc = 0; nc < 8; nc++) {
                uint32_t row = (uint32_t)(nc * 8) + ln7;
                uint32_t g = (uint32_t)(kc2 * 4) + (uint32_t)(lane >> 3);
                uint32_t gs = (g & 8u) | ((g & 7u) ^ (row & 7u));
                uint32_t addr = sb + row * 256u + gs * 16u;
                uint32_t kh4[4], kl4[4];
                LDSM_X4(kh4, addr);
                LDSM_X4(kl4, addr + 16384u);
                MMA_BF16(s[nc], qh[2 * kc2],     &kh4[0]);
                MMA_BF16(s[nc], ql[2 * kc2],     &kh4[0]);
                MMA_BF16(s[nc], qh[2 * kc2],     &kl4[0]);
                MMA_BF16(s[nc], qh[2 * kc2 + 1], &kh4[2]);
                MMA_BF16(s[nc], ql[2 * kc2 + 1], &kh4[2]);
                MMA_BF16(s[nc], qh[2 * kc2 + 1], &kl4[2]);
            }
        }

        // ---- mask ----
        if ((kt + 64 > Tk) || (causal && (kt + 63 >= qw))) {
#pragma unroll
            for (int nc = 0; nc < 8; nc++) {
#pragma unroll
                for (int e = 0; e < 4; e++) {
                    int kk = kt + nc * 8 + c2 + (e & 1);
                    int qr = qw + r0 + ((e >= 2) ? 8 : 0);
                    if (kk >= Tk || (causal && kk > qr)) s[nc][e] = -1e30f;
                }
            }
        }

        // ---- online softmax ----
        float mt0 = -1e30f, mt1 = -1e30f;
#pragma unroll
        for (int nc = 0; nc < 8; nc++) {
            mt0 = fmaxf(mt0, fmaxf(s[nc][0], s[nc][1]));
            mt1 = fmaxf(mt1, fmaxf(s[nc][2], s[nc][3]));
        }
        mt0 = fmaxf(mt0, __shfl_xor_sync(0xffffffffu, mt0, 1));
        mt0 = fmaxf(mt0, __shfl_xor_sync(0xffffffffu, mt0, 2));
        mt1 = fmaxf(mt1, __shfl_xor_sync(0xffffffffu, mt1, 1));
        mt1 = fmaxf(mt1, __shfl_xor_sync(0xffffffffu, mt1, 2));
        float mn0 = fmaxf(m0v, mt0), mn1 = fmaxf(m1v, mt1);
        float corr0 = __expf(m0v - mn0), corr1 = __expf(m1v - mn1);
        m0v = mn0; m1v = mn1;

        uint32_t ph[4][4], pl[4][4];
        float ps0 = 0.f, ps1 = 0.f;
#pragma unroll
        for (int nc = 0; nc < 8; nc++) {
            float p0 = __expf(s[nc][0] - mn0);
            float p1 = __expf(s[nc][1] - mn0);
            float p2 = __expf(s[nc][2] - mn1);
            float p3 = __expf(s[nc][3] - mn1);
            ps0 += p0 + p1; ps1 += p2 + p3;
            uint32_t h01, l01, h23, l23;
            split2(p0, p1, h01, l01);
            split2(p2, p3, h23, l23);
            int kc = nc >> 1;
            if ((nc & 1) == 0) { ph[kc][0] = h01; ph[kc][1] = h23; pl[kc][0] = l01; pl[kc][1] = l23; }
            else               { ph[kc][2] = h01; ph[kc][3] = h23; pl[kc][2] = l01; pl[kc][3] = l23; }
        }
        ps0 += __shfl_xor_sync(0xffffffffu, ps0, 1);
        ps0 += __shfl_xor_sync(0xffffffffu, ps0, 2);
        ps1 += __shfl_xor_sync(0xffffffffu, ps1, 1);
        ps1 += __shfl_xor_sync(0xffffffffu, ps1, 2);
        l0v = l0v * corr0 + ps0;
        l1v = l1v * corr1 + ps1;

#pragma unroll
        for (int n = 0; n < 16; n++) {
            o[n][0] *= corr0; o[n][1] *= corr0;
            o[n][2] *= corr1; o[n][3] *= corr1;
        }

        // ---- O += P V ----
#pragma unroll
        for (int kc = 0; kc < 4; kc++) {
            uint32_t row = (uint32_t)(kc * 16) + ((uint32_t)((lane >> 3) & 1)) * 8u + ln7;
#pragma unroll
            for (int dp = 0; dp < 8; dp++) {
                uint32_t g = (uint32_t)(dp * 2) + (uint32_t)(lane >> 4);
                uint32_t gs = (g & 8u) | ((g & 7u) ^ (row & 7u));
                uint32_t addr = sb + 32768u + row * 256u + gs * 16u;
                uint32_t vh4[4], vl4[4];
                LDSM_X4_T(vh4, addr);
                LDSM_X4_T(vl4, addr + 16384u);
                MMA_BF16(o[2 * dp],     ph[kc], &vh4[0]);
                MMA_BF16(o[2 * dp],     pl[kc], &vh4[0]);
                MMA_BF16(o[2 * dp],     ph[kc], &vl4[0]);
                MMA_BF16(o[2 * dp + 1], ph[kc], &vh4[2]);
                MMA_BF16(o[2 * dp + 1], pl[kc], &vh4[2]);
                MMA_BF16(o[2 * dp + 1], ph[kc], &vl4[2]);
            }
        }
    }

    // ---- epilogue ----
    float gate = gatep ? *gatep : 1.f;
    float sc0 = gate / l0v, sc1 = gate / l1v;
#pragma unroll
    for (int n = 0; n < 16; n++) {
        int gc = n * 8 + c2;
        long off0 = qbase + (long)(qw + r0) * 128 + gc;
        long off1 = off0 + 8 * 128;
        float2 v0 = make_float2(o[n][0] * sc0, o[n][1] * sc0);
        float2 v1 = make_float2(o[n][2] * sc1, o[n][3] * sc1);
        if (accum) {
            float2 p0 = *(const float2*)&Out[off0];
            float2 p1 = *(const float2*)&Out[off1];
            v0.x += p0.x; v0.y += p0.y;
            v1.x += p1.x; v1.y += p1.y;
        }
        *(float2*)&Out[off0] = v0;
        *(float2*)&Out[off1] = v1;
    }
}

// ================= transpose: in[R,C] -> out[C,R] =================
__global__ void transpose_kernel(const float* __restrict__ in, float* __restrict__ out, int R, int C)
{
    __shared__ float t[32][33];
    int bx = blockIdx.x * 32, by = blockIdx.y * 32;
    int x = bx + threadIdx.x;
#pragma unroll
    for (int j = 0; j < 32; j += 8) {
        int y = by + threadIdx.y + j;
        if (x < C && y < R) t[threadIdx.y + j][threadIdx.x] = in[(long)y * C + x];
    }
    __syncthreads();
    int x2 = by + threadIdx.x;
#pragma unroll
    for (int j = 0; j < 32; j += 8) {
        int y2 = bx + threadIdx.y + j;
        if (x2 < R && y2 < C) out[(long)y2 * R + x2] = t[threadIdx.x][threadIdx.y + j];
    }
}

// ================= rmsnorm per row =================
__global__ void rmsnorm_kernel(const float* __restrict__ in, const float* __restrict__ w,
                               float* __restrict__ out, int N)
{
    int row = blockIdx.x;
    const float* x = in + (long)row * N;
    float ss = 0.f;
    for (int c = threadIdx.x; c < N; c += 256) { float v = x[c]; ss = fmaf(v, v, ss); }
    __shared__ float sh[32];
    int lane = threadIdx.x & 31, wid = threadIdx.x >> 5;
#pragma unroll
    for (int o = 16; o; o >>= 1) ss += __shfl_xor_sync(0xffffffffu, ss, o);
    if (lane == 0) sh[wid] = ss;
    __syncthreads();
    float tot = (threadIdx.x < 8) ? sh[threadIdx.x] : 0.f;
    if (wid == 0) {
#pragma unroll
        for (int o = 16; o; o >>= 1) tot += __shfl_xor_sync(0xffffffffu, tot, o);
    }
    __shared__ float ssc;
    if (threadIdx.x == 0) ssc = rsqrtf(tot / (float)N + 1e-5f);
    __syncthreads();
    float sc = ssc;
    float* o = out + (long)row * N;
    for (int c = threadIdx.x; c < N; c += 256) o[c] = x[c] * sc * w[c];
}

// ================= split qkv + rope =================
__global__ void split_rope_kernel(const float* __restrict__ qkv,
                                  const float* __restrict__ cos_, const float* __restrict__ sin_,
                                  float* __restrict__ q, float* __restrict__ k, float* __restrict__ v)
{
    int idx = blockIdx.x * blockDim.x + threadIdx.x;
    if (idx >= BB * TT * NH * 64) return;
    int i = idx & 63;
    int h = (idx >> 6) & 31;
    int t = (idx >> 11) & 1023;
    int b = idx >> 21;
    long base = ((long)(b * TT + t)) * (3 * CC) + h * HS + 2 * i;
    float q0 = qkv[base],        q1 = qkv[base + 1];
    float k0 = qkv[base + CC],   k1 = qkv[base + CC + 1];
    float v0 = qkv[base + 2*CC], v1 = qkv[base + 2*CC + 1];
    float c = cos_[t * 64 + i], s = sin_[t * 64 + i];
    long ob = ((long)((b * NH + h) * TT + t)) * HS + 2 * i;
    q[ob] = q0 * c - q1 * s;  q[ob + 1] = q1 * c + q0 * s;
    k[ob] = k0 * c - k1 * s;  k[ob + 1] = k1 * c + k0 * s;
    v[ob] = v0;               v[ob + 1] = v1;
}

// ================= adapter split =================
__global__ void adapter_split_kernel(const float* __restrict__ aqkv,
                                     float* __restrict__ ak, float* __restrict__ av)
{
    int idx = blockIdx.x * blockDim.x + threadIdx.x;
    if (idx >= NH * ALEN * HS) return;
    int d = idx & 127;
    int a = (idx >> 7) % ALEN;
    int h = idx / (ALEN * HS);
    ak[idx] = aqkv[(long)a * (3 * CC) + CC     + h * HS + d];
    av[idx] = aqkv[(long)a * (3 * CC) + 2 * CC + h * HS + d];
}

// ================= assemble pk/pv =================
__global__ void fill_pkv_kernel(const float* __restrict__ wflat, const float* __restrict__ pad,
                                float* __restrict__ pkv)
{
    int idx = blockIdx.x * blockDim.x + threadIdx.x;
    if (idx >= BB * NH * AT * HS) return;
    int d = idx & 127;
    int t = (idx >> 7) % AT;
    int h = (idx / (HS * AT)) & 31;
    int b = idx / (HS * AT * NH);
    float v;
    if (h < NWH && d < WHD)
        v = wflat[(long)b * (AT * AD) + h * (AT * WHD) + t * WHD + d];
    else
        v = pad[((long)b * AT + t) * HS + d];
    pkv[idx] = v;
}

// ================= head mix =================
__global__ __launch_bounds__(256) void headmix_kernel(const float* __restrict__ q2a,
                                                      const float* __restrict__ w,
                                                      float* __restrict__ q2)
{
    int bt = blockIdx.x;
    int b = bt >> 10, t = bt & 1023;
    __shared__ float sm[NH * HS];
    __shared__ float ws[NH * NH];
    for (int i = threadIdx.x; i < NH * HS; i += 256) {
        int h = i >> 7, d = i & 127;
        sm[i] = q2a[(((long)(b * NH + h)) * TT + t) * HS + d];
    }
    for (int i = threadIdx.x; i < NH * NH; i += 256) ws[i] = w[i];
    __syncthreads();
    for (int i = threadIdx.x; i < NH * HS; i += 256) {
        int g = i >> 7, d = i & 127;
        float acc = 0.f;
#pragma unroll
        for (int h = 0; h < NH; h++) acc = fmaf(sm[h * HS + d], ws[h * NH + g], acc);
        q2[(((long)(b * NH + g)) * TT + t) * HS + d] = acc;
    }
}

// ================= [B,NH,T,HS] -> [B,T,C] =================
__global__ void transpose_y_kernel(const float* __restrict__ y, float* __restrict__ out)
{
    int idx = blockIdx.x * blockDim.x + threadIdx.x;
    if (idx >= BB * TT * CC) return;
    int d = idx & 127;
    int h = (idx >> 7) & 31;
    int t = (idx >> 12) & 1023;
    int b = idx >> 22;
    out[idx] = y[(((long)(b * NH + h)) * TT + t) * HS + d];
}

// ================= host launcher =================
static float* symp(const void* symbol)
{
    void* p = nullptr;
    cudaGetSymbolAddress(&p, symbol);
    return (float*)p;
}

static inline void gemm_tc(const float* A, const float* Bt, float* C,
                           int M, int N, int K, const float* bias, int act)
{
    dim3 grid((N + 127) / 128, (M + 127) / 128);
    gemm_bf16s_kernel<<<grid, 256, GEMM_SMEM_BYTES>>>(A, Bt, C, M, N, K, bias, act);
}

extern "C" void kernel_launch(void* const* d_in, const int* in_sizes, int n_in,
                              void* d_out, int out_size)
{
    (void)in_sizes; (void)n_in; (void)out_size;
    const float* x        = (const float*)d_in[0];
    const float* audio    = (const float*)d_in[1];
    const float* rope_cos = (const float*)d_in[2];
    const float* rope_sin = (const float*)d_in[3];
    const float* pad_k    = (const float*)d_in[6];
    const float* pad_v    = (const float*)d_in[7];
    const float* c_attn_w = (const float*)d_in[8];
    const float* c_proj_w = (const float*)d_in[9];
    const float* adapter  = (const float*)d_in[10];
    const float* gating   = (const float*)d_in[11];
    const float* rms_gate = (const float*)d_in[12];
    const float* rms_key  = (const float*)d_in[13];
    const float* rms_val  = (const float*)d_in[14];
    const float* proj_dn  = (const float*)d_in[15];
    const float* proj_up  = (const float*)d_in[16];
    const float* pq128    = (const float*)d_in[17];
    const float* pq32     = (const float*)d_in[18];
    const float* pgating  = (const float*)d_in[19];
    const float* wkw      = (const float*)d_in[20];
    const float* wvw      = (const float*)d_in[21];
    const float* wvb      = (const float*)d_in[22];
    float* out = (float*)d_out;

    float *qkv = symp(g_qkv), *q = symp(g_q), *k = symp(g_k), *v = symp(g_v), *y = symp(g_y);
    float *pref = symp(g_pref), *aqkv = symp(g_aqkv), *ak = symp(g_ak), *av = symp(g_av);
    float *wkn = symp(g_wkn), *wvn = symp(g_wvn), *hid = symp(g_hid), *wk = symp(g_wk), *wv = symp(g_wv);
    float *pk = symp(g_pk), *pv = symp(g_pv), *q2a = symp(g_q2a), *q2 = symp(g_q2), *ybt = symp(g_ybt);
    float *attn_wt = symp(g_attn_wt), *proj_wt = symp(g_proj_wt);
    float *wkw_t = symp(g_wkw_t), *wvw_t = symp(g_wvw_t);
    float *pdn_t = symp(g_pdn_t), *pup_t = symp(g_pup_t), *pq128_t = symp(g_pq128_t);

    cudaFuncSetAttribute(gemm_bf16s_kernel, cudaFuncAttributeMaxDynamicSharedMemorySize,
                         GEMM_SMEM_BYTES);
    cudaFuncSetAttribute(attn_mma_kernel, cudaFuncAttributeMaxDynamicSharedMemorySize,
                         ATTN_SMEM_BYTES);

    const int M = BB * TT;            // 2048
    const int MA = BB * AT;           // 3000
    dim3 tb(32, 8);

    // 0) weight transposes (W[K,N] -> Wt[N,K])
    transpose_kernel<<<dim3((3*CC + 31)/32, (CC + 31)/32), tb>>>(c_attn_w, attn_wt, CC, 3*CC);
    transpose_kernel<<<dim3((CC + 31)/32, (CC + 31)/32), tb>>>(c_proj_w, proj_wt, CC, CC);
    transpose_kernel<<<dim3((AD + 31)/32, (AD + 31)/32), tb>>>(wkw, wkw_t, AD, AD);
    transpose_kernel<<<dim3((AD + 31)/32, (AD + 31)/32), tb>>>(wvw, wvw_t, AD, AD);
    transpose_kernel<<<dim3((DHID + 31)/32, (AD + 31)/32), tb>>>(proj_dn, pdn_t, AD, DHID);
    transpose_kernel<<<dim3((AD + 31)/32, (DHID + 31)/32), tb>>>(proj_up, pup_t, DHID, AD);
    transpose_kernel<<<dim3((HS + 31)/32, (HS + 31)/32), tb>>>(pq128, pq128_t, HS, HS);

    // 1) qkv = x @ c_attn_w
    gemm_tc(x, attn_wt, qkv, M, 3*CC, CC, nullptr, 0);

    // 2) split + rope
    {
        int tot = BB * TT * NH * 64;
        split_rope_kernel<<<(tot + 255) / 256, 256>>>(qkv, rope_cos, rope_sin, q, k, v);
    }

    // 3) causal self-attention -> y
    attn_mma_kernel<<<dim3(TT/64, NH, BB), 128, ATTN_SMEM_BYTES>>>(
        q, k, v, y, NH, TT, TT, (long)NH*TT*HS, (long)TT*HS, 1, nullptr, 0);

    // 4) adapter branch
    rmsnorm_kernel<<<ALEN, 256>>>(adapter, rms_gate, pref, CC);
    gemm_tc(pref, attn_wt, aqkv, ALEN, 3*CC, CC, nullptr, 0);
    adapter_split_kernel<<<(NH*ALEN*HS + 255) / 256, 256>>>(aqkv, ak, av);
    attn_mma_kernel<<<dim3(TT/64, NH, BB), 128, ATTN_SMEM_BYTES>>>(
        q, ak, av, y, NH, TT, ALEN, 0L, (long)ALEN*HS, 0, gating, 1);

    // 5) whisper key path
    gemm_tc(audio, wkw_t, wkn, MA, AD, AD, nullptr, 0);
    rmsnorm_kernel<<<MA, 256>>>(wkn, rms_key, wkn, AD);
    gemm_tc(wkn, pdn_t, hid, MA, DHID, AD, nullptr, 1);
    gemm_tc(hid, pup_t, wk, MA, AD, DHID, nullptr, 0);

    // 6) whisper value path
    gemm_tc(audio, wvw_t, wvn, MA, AD, AD, wvb, 0);
    rmsnorm_kernel<<<MA, 256>>>(wvn, rms_val, wvn, AD);
    gemm_tc(wvn, pdn_t, hid, MA, DHID, AD, nullptr, 1);
    gemm_tc(hid, pup_t, wv, MA, AD, DHID, nullptr, 0);

    // 7) assemble pk/pv
    {
        int tot = BB * NH * AT * HS;
        fill_pkv_kernel<<<(tot + 255) / 256, 256>>>(wk, pad_k, pk);
        fill_pkv_kernel<<<(tot + 255) / 256, 256>>>(wv, pad_v, pv);
    }

    // 8) q2 = (q @ proj_q128) head-mixed by proj_q32
    gemm_tc(q, pq128_t, q2a, BB*NH*TT, HS, HS, nullptr, 0);
    headmix_kernel<<<BB * TT, 256>>>(q2a, pq32, q2);

    // 9) whisper cross-attention -> y += proj_gating * wy
    attn_mma_kernel<<<dim3(TT/64, NH, BB), 128, ATTN_SMEM_BYTES>>>(
        q2, pk, pv, y, NH, TT, AT, (long)NH*AT*HS, (long)AT*HS, 0, pgating, 1);

    // 10) transpose + output projection
    {
        int tot = BB * TT * CC;
        transpose_y_kernel<<<(tot + 255) / 256, 256>>>(y, ybt);
    }
    gemm_tc(ybt, proj_wt, out, M, CC, CC, nullptr, 0);
}

// round 5
// speedup vs baseline: 2.9197x; 1.0214x over previous
#include <cuda_runtime.h>
#include <cuda_bf16.h>
#include <math.h>
#include <stdint.h>

// ---------------- problem constants ----------------
#define BB 2
#define TT 1024
#define CC 4096
#define NH 32
#define HS 128
#define ALEN 10
#define AT 1500
#define AD 1280
#define NWH 20
#define WHD 64
#define DHID 80           // AD/16
#define ATT_SCALE 0.08838834764831845f   // 1/sqrt(128)

// ---------------- scratch buffers (device globals; no allocation) ----------------
__device__ float g_qkv [BB*TT*3*CC];
__device__ float g_q   [BB*NH*TT*HS];
__device__ float g_k   [BB*NH*TT*HS];
__device__ float g_v   [BB*NH*TT*HS];
__device__ float g_y   [BB*NH*TT*HS];
__device__ float g_pref[ALEN*CC];
__device__ float g_aqkv[ALEN*3*CC];
__device__ float g_ak  [NH*ALEN*HS];
__device__ float g_av  [NH*ALEN*HS];
__device__ float g_wkn [BB*AT*AD];
__device__ float g_wvn [BB*AT*AD];
__device__ float g_hid [BB*AT*DHID];
__device__ float g_wk  [BB*AT*AD];
__device__ float g_wv  [BB*AT*AD];
__device__ float g_pk  [BB*NH*AT*HS];
__device__ float g_pv  [BB*NH*AT*HS];
__device__ float g_q2a [BB*NH*TT*HS];
__device__ float g_q2  [BB*NH*TT*HS];
__device__ float g_ybt [BB*TT*CC];

// ================= helpers =================
__device__ __forceinline__ uint32_t smem_u32(const void* p) {
    uint32_t a;
    asm("{ .reg .u64 t; cvta.to.shared.u64 t, %1; cvt.u32.u64 %0, t; }" : "=r"(a) : "l"(p));
    return a;
}

#define LDSM_X4(r, addr) \
    asm volatile("ldmatrix.sync.aligned.m8n8.x4.shared.b16 {%0,%1,%2,%3}, [%4];" \
        : "=r"((r)[0]), "=r"((r)[1]), "=r"((r)[2]), "=r"((r)[3]) : "r"(addr))
#define LDSM_X4_T(r, addr) \
    asm volatile("ldmatrix.sync.aligned.m8n8.x4.trans.shared.b16 {%0,%1,%2,%3}, [%4];" \
        : "=r"((r)[0]), "=r"((r)[1]), "=r"((r)[2]), "=r"((r)[3]) : "r"(addr))
#define MMA_BF16(c, a, b) \
    asm volatile("mma.sync.aligned.m16n8k16.row.col.f32.bf16.bf16.f32 " \
        "{%0,%1,%2,%3}, {%4,%5,%6,%7}, {%8,%9}, {%0,%1,%2,%3};" \
        : "+f"((c)[0]), "+f"((c)[1]), "+f"((c)[2]), "+f"((c)[3]) \
        : "r"((a)[0]), "r"((a)[1]), "r"((a)[2]), "r"((a)[3]), "r"((b)[0]), "r"((b)[1]))

// split a float4 into bf16 hi plane (4 bf16 = uint2) and residual lo plane
__device__ __forceinline__ void cvt_split4(const float4 v, uint2& hi, uint2& lo) {
    __nv_bfloat16 h0 = __float2bfloat16(v.x), h1 = __float2bfloat16(v.y);
    __nv_bfloat16 h2 = __float2bfloat16(v.z), h3 = __float2bfloat16(v.w);
    float r0 = v.x - __bfloat162float(h0), r1 = v.y - __bfloat162float(h1);
    float r2 = v.z - __bfloat162float(h2), r3 = v.w - __bfloat162float(h3);
    __nv_bfloat162 p01, p23, q01, q23;
    p01.x = h0; p01.y = h1; p23.x = h2; p23.y = h3;
    q01.x = __float2bfloat16(r0); q01.y = __float2bfloat16(r1);
    q23.x = __float2bfloat16(r2); q23.y = __float2bfloat16(r3);
    hi.x = *(uint32_t*)&p01; hi.y = *(uint32_t*)&p23;
    lo.x = *(uint32_t*)&q01; lo.y = *(uint32_t*)&q23;
}
__device__ __forceinline__ void split2(float a, float b, uint32_t& hi, uint32_t& lo) {
    __nv_bfloat162 h;
    h.x = __float2bfloat16(a); h.y = __float2bfloat16(b);
    float ra = a - __bfloat162float(h.x);
    float rb = b - __bfloat162float(h.y);
    __nv_bfloat162 l;
    l.x = __float2bfloat16(ra); l.y = __float2bfloat16(rb);
    hi = *(uint32_t*)&h; lo = *(uint32_t*)&l;
}

// ================= bf16-split tensor-core GEMM, B in natural [K,N] layout ====
// C[M,N] = A[M,K] @ W[K,N].
// CTA tile 128x128, BK=32, double-buffered (32KB/buffer):
//   A planes: 128 rows x 128B (hi granules 0-3, lo granules 4-7, XOR-swz by row&7)
//   B planes: 32 k-rows x 256B hi (offset +16K) and lo (+24K), granule XOR-swz.
// B fragments fetched via ldmatrix.trans (k-rows addressed).
#define GEMM_SMEM_BYTES 65536

__global__ __launch_bounds__(256, 1) void gemm_bf16s_kernel(
    const float* __restrict__ A, const float* __restrict__ B, float* __restrict__ C,
    int M, int N, int K, const float* __restrict__ bias, int act)
{
    extern __shared__ __align__(128) unsigned char smem[];
    const uint32_t sbase = smem_u32(smem);
    const int tid = threadIdx.x;
    const int lane = tid & 31, warp = tid >> 5;
    const int wm = warp & 1, wn = warp >> 1;
    const int m0 = blockIdx.y * 128, n0 = blockIdx.x * 128;
    const int nkt = (K + 31) / 32;

    float acc[4][4][4];
#pragma unroll
    for (int i = 0; i < 4; i++)
#pragma unroll
        for (int j = 0; j < 4; j++)
#pragma unroll
            for (int e = 0; e < 4; e++) acc[i][j][e] = 0.f;

    float4 aReg[4], bReg[4];

    auto glob_load = [&](int kt) {
#pragma unroll
        for (int q = 0; q < 4; q++) {
            int idx = q * 256 + tid;
            // ---- A: row-major [M,K], tile 128 x 32 ----
            {
                int r = idx >> 3, c = idx & 7;
                int gk = kt * 32 + c * 4;
                float4 av = make_float4(0.f, 0.f, 0.f, 0.f);
                int gr = m0 + r;
                if (gr < M) {
                    const float* p = A + (long)gr * K + gk;
                    if (gk + 3 < K) av = *(const float4*)p;
                    else {
                        if (gk + 0 < K) av.x = p[0];
                        if (gk + 1 < K) av.y = p[1];
                        if (gk + 2 < K) av.z = p[2];
                    }
                }
                aReg[q] = av;
            }
            // ---- B: row-major [K,N], tile 32 x 128 ----
            {
                int r = idx >> 5, c = idx & 31;
                int gk = kt * 32 + r;
                int gn = n0 + c * 4;
                float4 bv = make_float4(0.f, 0.f, 0.f, 0.f);
                if (gk < K) {
                    const float* p = B + (long)gk * N + gn;
                    if (gn + 3 < N) bv = *(const float4*)p;
                    else {
                        if (gn + 0 < N) bv.x = p[0];
                        if (gn + 1 < N) bv.y = p[1];
                        if (gn + 2 < N) bv.z = p[2];
                    }
                }
                bReg[q] = bv;
            }
        }
    };

    auto smem_store = [&](int buf) {
        uint32_t aB = buf * 32768u;
        uint32_t bB = aB + 16384u;
#pragma unroll
        for (int q = 0; q < 4; q++) {
            int idx = q * 256 + tid;
            uint2 hi, lo;
            // A
            {
                int r = idx >> 3, c = idx & 7;
                uint32_t sub = (uint32_t)(c & 1) * 8u;
                uint32_t gh = (uint32_t)((c >> 1) ^ (r & 7));
                uint32_t gl = (uint32_t)((4 + (c >> 1)) ^ (r & 7));
                cvt_split4(aReg[q], hi, lo);
                *(uint2*)(smem + aB + (uint32_t)r * 128u + gh * 16u + sub) = hi;
                *(uint2*)(smem + aB + (uint32_t)r * 128u + gl * 16u + sub) = lo;
            }
            // B
            {
                int r = idx >> 5, c = idx & 31;
                uint32_t g = (uint32_t)(c >> 1), sub = (uint32_t)(c & 1) * 8u;
                uint32_t gs = (g & 8u) | ((g & 7u) ^ ((uint32_t)r & 7u));
                uint32_t off = (uint32_t)r * 256u + gs * 16u + sub;
                cvt_split4(bReg[q], hi, lo);
                *(uint2*)(smem + bB + off)         = hi;
                *(uint2*)(smem + bB + 8192u + off) = lo;
            }
        }
    };

    auto compute = [&](int buf) {
        uint32_t aB = sbase + buf * 32768u;
        uint32_t bB = aB + 16384u;
#pragma unroll
        for (int ks = 0; ks < 2; ks++) {
            uint32_t kg = (uint32_t)ks * 2u;
            uint32_t ah[4][4], al[4][4];
            uint32_t bh4[2][4], bl4[2][4];
#pragma unroll
            for (int i = 0; i < 4; i++) {
                uint32_t row = (uint32_t)(wm * 64 + i * 16 + (lane & 15));
                uint32_t gcol = kg + (uint32_t)(lane >> 4);
                uint32_t rb = aB + row * 128u;
                LDSM_X4(ah[i], rb + ((gcol ^ (row & 7u)) << 4));
                LDSM_X4(al[i], rb + (((gcol + 4u) ^ (row & 7u)) << 4));
            }
#pragma unroll
            for (int j2 = 0; j2 < 2; j2++) {
                uint32_t row = (uint32_t)(ks * 16) + (((uint32_t)lane >> 3) & 1u) * 8u + ((uint32_t)lane & 7u);
                uint32_t g = (uint32_t)(wn * 4 + j2 * 2) + ((uint32_t)lane >> 4);
                uint32_t gs = (g & 8u) | ((g & 7u) ^ (row & 7u));
                uint32_t addr = bB + row * 256u + gs * 16u;
                LDSM_X4_T(bh4[j2], addr);
                LDSM_X4_T(bl4[j2], addr + 8192u);
            }
#pragma unroll
            for (int i = 0; i < 4; i++)
#pragma unroll
                for (int j = 0; j < 4; j++) {
                    uint32_t* bh = &bh4[j >> 1][(j & 1) * 2];
                    uint32_t* bl = &bl4[j >> 1][(j & 1) * 2];
                    MMA_BF16(acc[i][j], ah[i], bh);
                    MMA_BF16(acc[i][j], ah[i], bl);
                    MMA_BF16(acc[i][j], al[i], bh);
                }
        }
    };

    glob_load(0);
    smem_store(0);
    __syncthreads();
    for (int kt = 0; kt < nkt; kt++) {
        int buf = kt & 1;
        if (kt + 1 < nkt) glob_load(kt + 1);
        compute(buf);
        __syncthreads();
        if (kt + 1 < nkt) {
            smem_store(buf ^ 1);
            __syncthreads();
        }
    }

#pragma unroll
    for (int i = 0; i < 4; i++) {
#pragma unroll
        for (int j = 0; j < 4; j++) {
            int gc = n0 + wn * 32 + j * 8 + (lane & 3) * 2;
            float b0v = 0.f, b1v = 0.f;
            if (bias) {
                if (gc < N)     b0v = bias[gc];
                if (gc + 1 < N) b1v = bias[gc + 1];
            }
#pragma unroll
            for (int half = 0; half < 2; half++) {
                int gr = m0 + wm * 64 + i * 16 + (lane >> 2) + half * 8;
                if (gr >= M) continue;
                float v0 = acc[i][j][half * 2 + 0] + b0v;
                float v1 = acc[i][j][half * 2 + 1] + b1v;
                if (act == 1) {
                    v0 = v0 / (1.f + __expf(-v0));
                    v1 = v1 / (1.f + __expf(-v1));
                }
                if (gc + 1 < N) {
                    *(float2*)&C[(long)gr * N + gc] = make_float2(v0, v1);
                } else if (gc < N) {
                    C[(long)gr * N + gc] = v0;
                }
            }
        }
    }
}

// ================= tensor-core flash attention (unchanged from R3) =================
#define ATTN_SMEM_BYTES 65536

__global__ __launch_bounds__(128, 1) void attn_mma_kernel(
    const float* __restrict__ Q, const float* __restrict__ K, const float* __restrict__ V,
    float* __restrict__ Out, int H, int Tq, int Tk,
    long kvbs, long kvhs, int causal, const float* __restrict__ gatep, int accum)
{
    extern __shared__ __align__(128) unsigned char smem[];
    const uint32_t sb = smem_u32(smem);
    const int tid = threadIdx.x, lane = tid & 31, warp = tid >> 5;
    const int q0 = blockIdx.x * 64, h = blockIdx.y, b = blockIdx.z;
    const long qbase = ((long)(b * H + h)) * Tq * 128;
    const long kbase = (long)b * kvbs + (long)h * kvhs;
    const int qw = q0 + warp * 16;
    const int r0 = lane >> 2;
    const int c2 = (lane & 3) * 2;
    const uint32_t ln7 = lane & 7u;

    uint32_t qh[8][4], ql[8][4];
    {
        const float* qp0 = Q + qbase + (long)(qw + r0) * 128;
        const float* qp1 = qp0 + 8 * 128;
#pragma unroll
        for (int kc = 0; kc < 8; kc++) {
            float2 x0 = *(const float2*)&qp0[kc * 16 + c2];
            float2 x1 = *(const float2*)&qp1[kc * 16 + c2];
            float2 x2 = *(const float2*)&qp0[kc * 16 + c2 + 8];
            float2 x3 = *(const float2*)&qp1[kc * 16 + c2 + 8];
            split2(x0.x * ATT_SCALE, x0.y * ATT_SCALE, qh[kc][0], ql[kc][0]);
            split2(x1.x * ATT_SCALE, x1.y * ATT_SCALE, qh[kc][1], ql[kc][1]);
            split2(x2.x * ATT_SCALE, x2.y * ATT_SCALE, qh[kc][2], ql[kc][2]);
            split2(x3.x * ATT_SCALE, x3.y * ATT_SCALE, qh[kc][3], ql[kc][3]);
        }
    }

    float o[16][4];
#pragma unroll
    for (int n = 0; n < 16; n++)
#pragma unroll
        for (int e = 0; e < 4; e++) o[n][e] = 0.f;
    float m0v = -1e30f, m1v = -1e30f, l0v = 0.f, l1v = 0.f;

    const int kend = causal ? min(Tk, q0 + 64) : Tk;

    for (int kt = 0; kt < kend; kt += 64) {
        __syncthreads();
#pragma unroll
        for (int it = 0; it < 16; it++) {
            int idx = it * 128 + tid;
            int r = idx >> 5, c4 = idx & 31;
            float4 kvv = make_float4(0.f, 0.f, 0.f, 0.f);
            float4 vvv = make_float4(0.f, 0.f, 0.f, 0.f);
            if (kt + r < Tk) {
                long off = kbase + (long)(kt + r) * 128 + c4 * 4;
                kvv = *(const float4*)&K[off];
                vvv = *(const float4*)&V[off];
            }
            uint32_t g = (uint32_t)(c4 >> 1), sub = (uint32_t)(c4 & 1) * 8u;
            uint32_t gs = (g & 8u) | ((g & 7u) ^ ((uint32_t)r & 7u));
            uint32_t ro = (uint32_t)r * 256u + gs * 16u + sub;
            uint2 hi, lo;
            cvt_split4(kvv, hi, lo);
            *(uint2*)(smem + ro)          = hi;
            *(uint2*)(smem + 16384u + ro) = lo;
            cvt_split4(vvv, hi, lo);
            *(uint2*)(smem + 32768u + ro) = hi;
            *(uint2*)(smem + 49152u + ro) = lo;
        }
        __syncthreads();

        float s[8][4];
#pragma unroll
        for (int n = 0; n < 8; n++)
#pragma unroll
            for (int e = 0; e < 4; e++) s[n][e] = 0.f;

#pragma unroll
        for (int kc2 = 0; kc2 < 4; kc2++) {
#pragma unroll
            for (int nc = 0; nc < 8; nc++) {
                uint32_t row = (uint32_t)(nc * 8) + ln7;
                uint32_t g = (uint32_t)(kc2 * 4) + (uint32_t)(lane >> 3);
                uint32_t gs = (g & 8u) | ((g & 7u) ^ (row & 7u));
                uint32_t addr = sb + row * 256u + gs * 16u;
                uint32_t kh4[4], kl4[4];
                LDSM_X4(kh4, addr);
                LDSM_X4(kl4, addr + 16384u);
                MMA_BF16(s[nc], qh[2 * kc2],     &kh4[0]);
                MMA_BF16(s[nc], ql[2 * kc2],     &kh4[0]);
                MMA_BF16(s[nc], qh[2 * kc2],     &kl4[0]);
                MMA_BF16(s[nc], qh[2 * kc2 + 1], &kh4[2]);
                MMA_BF16(s[nc], ql[2 * kc2 + 1], &kh4[2]);
                MMA_BF16(s[nc], qh[2 * kc2 + 1], &kl4[2]);
            }
        }

        if ((kt + 64 > Tk) || (causal && (kt + 63 >= qw))) {
#pragma unroll
            for (int nc = 0; nc < 8; nc++) {
#pragma unroll
                for (int e = 0; e < 4; e++) {
                    int kk = kt + nc * 8 + c2 + (e & 1);
                    int qr = qw + r0 + ((e >= 2) ? 8 : 0);
                    if (kk >= Tk || (causal && kk > qr)) s[nc][e] = -1e30f;
                }
            }
        }

        float mt0 = -1e30f, mt1 = -1e30f;
#pragma unroll
        for (int nc = 0; nc < 8; nc++) {
            mt0 = fmaxf(mt0, fmaxf(s[nc][0], s[nc][1]));
            mt1 = fmaxf(mt1, fmaxf(s[nc][2], s[nc][3]));
        }
        mt0 = fmaxf(mt0, __shfl_xor_sync(0xffffffffu, mt0, 1));
        mt0 = fmaxf(mt0, __shfl_xor_sync(0xffffffffu, mt0, 2));
        mt1 = fmaxf(mt1, __shfl_xor_sync(0xffffffffu, mt1, 1));
        mt1 = fmaxf(mt1, __shfl_xor_sync(0xffffffffu, mt1, 2));
        float mn0 = fmaxf(m0v, mt0), mn1 = fmaxf(m1v, mt1);
        float corr0 = __expf(m0v - mn0), corr1 = __expf(m1v - mn1);
        m0v = mn0; m1v = mn1;

        uint32_t ph[4][4], pl[4][4];
        float ps0 = 0.f, ps1 = 0.f;
#pragma unroll
        for (int nc = 0; nc < 8; nc++) {
            float p0 = __expf(s[nc][0] - mn0);
            float p1 = __expf(s[nc][1] - mn0);
            float p2 = __expf(s[nc][2] - mn1);
            float p3 = __expf(s[nc][3] - mn1);
            ps0 += p0 + p1; ps1 += p2 + p3;
            uint32_t h01, l01, h23, l23;
            split2(p0, p1, h01, l01);
            split2(p2, p3, h23, l23);
            int kc = nc >> 1;
            if ((nc & 1) == 0) { ph[kc][0] = h01; ph[kc][1] = h23; pl[kc][0] = l01; pl[kc][1] = l23; }
            else               { ph[kc][2] = h01; ph[kc][3] = h23; pl[kc][2] = l01; pl[kc][3] = l23; }
        }
        ps0 += __shfl_xor_sync(0xffffffffu, ps0, 1);
        ps0 += __shfl_xor_sync(0xffffffffu, ps0, 2);
        ps1 += __shfl_xor_sync(0xffffffffu, ps1, 1);
        ps1 += __shfl_xor_sync(0xffffffffu, ps1, 2);
        l0v = l0v * corr0 + ps0;
        l1v = l1v * corr1 + ps1;

#pragma unroll
        for (int n = 0; n < 16; n++) {
            o[n][0] *= corr0; o[n][1] *= corr0;
            o[n][2] *= corr1; o[n][3] *= corr1;
        }

#pragma unroll
        for (int kc = 0; kc < 4; kc++) {
            uint32_t row = (uint32_t)(kc * 16) + ((uint32_t)((lane >> 3) & 1)) * 8u + ln7;
#pragma unroll
            for (int dp = 0; dp < 8; dp++) {
                uint32_t g = (uint32_t)(dp * 2) + (uint32_t)(lane >> 4);
                uint32_t gs = (g & 8u) | ((g & 7u) ^ (row & 7u));
                uint32_t addr = sb + 32768u + row * 256u + gs * 16u;
                uint32_t vh4[4], vl4[4];
                LDSM_X4_T(vh4, addr);
                LDSM_X4_T(vl4, addr + 16384u);
                MMA_BF16(o[2 * dp],     ph[kc], &vh4[0]);
                MMA_BF16(o[2 * dp],     pl[kc], &vh4[0]);
                MMA_BF16(o[2 * dp],     ph[kc], &vl4[0]);
                MMA_BF16(o[2 * dp + 1], ph[kc], &vh4[2]);
                MMA_BF16(o[2 * dp + 1], pl[kc], &vh4[2]);
                MMA_BF16(o[2 * dp + 1], ph[kc], &vl4[2]);
            }
        }
    }

    float gate = gatep ? *gatep : 1.f;
    float sc0 = gate / l0v, sc1 = gate / l1v;
#pragma unroll
    for (int n = 0; n < 16; n++) {
        int gc = n * 8 + c2;
        long off0 = qbase + (long)(qw + r0) * 128 + gc;
        long off1 = off0 + 8 * 128;
        float2 v0 = make_float2(o[n][0] * sc0, o[n][1] * sc0);
        float2 v1 = make_float2(o[n][2] * sc1, o[n][3] * sc1);
        if (accum) {
            float2 p0 = *(const float2*)&Out[off0];
            float2 p1 = *(const float2*)&Out[off1];
            v0.x += p0.x; v0.y += p0.y;
            v1.x += p1.x; v1.y += p1.y;
        }
        *(float2*)&Out[off0] = v0;
        *(float2*)&Out[off1] = v1;
    }
}

// ================= rmsnorm per row =================
__global__ void rmsnorm_kernel(const float* __restrict__ in, const float* __restrict__ w,
                               float* __restrict__ out, int N)
{
    int row = blockIdx.x;
    const float* x = in + (long)row * N;
    float ss = 0.f;
    for (int c = threadIdx.x; c < N; c += 256) { float v = x[c]; ss = fmaf(v, v, ss); }
    __shared__ float sh[32];
    int lane = threadIdx.x & 31, wid = threadIdx.x >> 5;
#pragma unroll
    for (int o = 16; o; o >>= 1) ss += __shfl_xor_sync(0xffffffffu, ss, o);
    if (lane == 0) sh[wid] = ss;
    __syncthreads();
    float tot = (threadIdx.x < 8) ? sh[threadIdx.x] : 0.f;
    if (wid == 0) {
#pragma unroll
        for (int o = 16; o; o >>= 1) tot += __shfl_xor_sync(0xffffffffu, tot, o);
    }
    __shared__ float ssc;
    if (threadIdx.x == 0) ssc = rsqrtf(tot / (float)N + 1e-5f);
    __syncthreads();
    float sc = ssc;
    float* o = out + (long)row * N;
    for (int c = threadIdx.x; c < N; c += 256) o[c] = x[c] * sc * w[c];
}

// ================= split qkv + rope =================
__global__ void split_rope_kernel(const float* __restrict__ qkv,
                                  const float* __restrict__ cos_, const float* __restrict__ sin_,
                                  float* __restrict__ q, float* __restrict__ k, float* __restrict__ v)
{
    int idx = blockIdx.x * blockDim.x + threadIdx.x;
    if (idx >= BB * TT * NH * 64) return;
    int i = idx & 63;
    int h = (idx >> 6) & 31;
    int t = (idx >> 11) & 1023;
    int b = idx >> 21;
    long base = ((long)(b * TT + t)) * (3 * CC) + h * HS + 2 * i;
    float q0 = qkv[base],        q1 = qkv[base + 1];
    float k0 = qkv[base + CC],   k1 = qkv[base + CC + 1];
    float v0 = qkv[base + 2*CC], v1 = qkv[base + 2*CC + 1];
    float c = cos_[t * 64 + i], s = sin_[t * 64 + i];
    long ob = ((long)((b * NH + h) * TT + t)) * HS + 2 * i;
    q[ob] = q0 * c - q1 * s;  q[ob + 1] = q1 * c + q0 * s;
    k[ob] = k0 * c - k1 * s;  k[ob + 1] = k1 * c + k0 * s;
    v[ob] = v0;               v[ob + 1] = v1;
}

// ================= adapter split =================
__global__ void adapter_split_kernel(const float* __restrict__ aqkv,
                                     float* __restrict__ ak, float* __restrict__ av)
{
    int idx = blockIdx.x * blockDim.x + threadIdx.x;
    if (idx >= NH * ALEN * HS) return;
    int d = idx & 127;
    int a = (idx >> 7) % ALEN;
    int h = idx / (ALEN * HS);
    ak[idx] = aqkv[(long)a * (3 * CC) + CC     + h * HS + d];
    av[idx] = aqkv[(long)a * (3 * CC) + 2 * CC + h * HS + d];
}

// ================= assemble pk/pv =================
__global__ void fill_pkv_kernel(const float* __restrict__ wflat, const float* __restrict__ pad,
                                float* __restrict__ pkv)
{
    int idx = blockIdx.x * blockDim.x + threadIdx.x;
    if (idx >= BB * NH * AT * HS) return;
    int d = idx & 127;
    int t = (idx >> 7) % AT;
    int h = (idx / (HS * AT)) & 31;
    int b = idx / (HS * AT * NH);
    float v;
    if (h < NWH && d < WHD)
        v = wflat[(long)b * (AT * AD) + h * (AT * WHD) + t * WHD + d];
    else
        v = pad[((long)b * AT + t) * HS + d];
    pkv[idx] = v;
}

// ================= head mix =================
__global__ __launch_bounds__(256) void headmix_kernel(const float* __restrict__ q2a,
                                                      const float* __restrict__ w,
                                                      float* __restrict__ q2)
{
    int bt = blockIdx.x;
    int b = bt >> 10, t = bt & 1023;
    __shared__ float sm[NH * HS];
    __shared__ float ws[NH * NH];
    for (int i = threadIdx.x; i < NH * HS; i += 256) {
        int h = i >> 7, d = i & 127;
        sm[i] = q2a[(((long)(b * NH + h)) * TT + t) * HS + d];
    }
    for (int i = threadIdx.x; i < NH * NH; i += 256) ws[i] = w[i];
    __syncthreads();
    for (int i = threadIdx.x; i < NH * HS; i += 256) {
        int g = i >> 7, d = i & 127;
        float acc = 0.f;
#pragma unroll
        for (int h = 0; h < NH; h++) acc = fmaf(sm[h * HS + d], ws[h * NH + g], acc);
        q2[(((long)(b * NH + g)) * TT + t) * HS + d] = acc;
    }
}

// ================= [B,NH,T,HS] -> [B,T,C] =================
__global__ void transpose_y_kernel(const float* __restrict__ y, float* __restrict__ out)
{
    int idx = blockIdx.x * blockDim.x + threadIdx.x;
    if (idx >= BB * TT * CC) return;
    int d = idx & 127;
    int h = (idx >> 7) & 31;
    int t = (idx >> 12) & 1023;
    int b = idx >> 22;
    out[idx] = y[(((long)(b * NH + h)) * TT + t) * HS + d];
}

// ================= host launcher =================
static float* symp(const void* symbol)
{
    void* p = nullptr;
    cudaGetSymbolAddress(&p, symbol);
    return (float*)p;
}

static inline void gemm_tc(const float* A, const float* B, float* C,
                           int M, int N, int K, const float* bias, int act)
{
    dim3 grid((N + 127) / 128, (M + 127) / 128);
    gemm_bf16s_kernel<<<grid, 256, GEMM_SMEM_BYTES>>>(A, B, C, M, N, K, bias, act);
}

extern "C" void kernel_launch(void* const* d_in, const int* in_sizes, int n_in,
                              void* d_out, int out_size)
{
    (void)in_sizes; (void)n_in; (void)out_size;
    const float* x        = (const float*)d_in[0];
    const float* audio    = (const float*)d_in[1];
    const float* rope_cos = (const float*)d_in[2];
    const float* rope_sin = (const float*)d_in[3];
    const float* pad_k    = (const float*)d_in[6];
    const float* pad_v    = (const float*)d_in[7];
    const float* c_attn_w = (const float*)d_in[8];
    const float* c_proj_w = (const float*)d_in[9];
    const float* adapter  = (const float*)d_in[10];
    const float* gating   = (const float*)d_in[11];
    const float* rms_gate = (const float*)d_in[12];
    const float* rms_key  = (const float*)d_in[13];
    const float* rms_val  = (const float*)d_in[14];
    const float* proj_dn  = (const float*)d_in[15];
    const float* proj_up  = (const float*)d_in[16];
    const float* pq128    = (const float*)d_in[17];
    const float* pq32     = (const float*)d_in[18];
    const float* pgating  = (const float*)d_in[19];
    const float* wkw      = (const float*)d_in[20];
    const float* wvw      = (const float*)d_in[21];
    const float* wvb      = (const float*)d_in[22];
    float* out = (float*)d_out;

    float *qkv = symp(g_qkv), *q = symp(g_q), *k = symp(g_k), *v = symp(g_v), *y = symp(g_y);
    float *pref = symp(g_pref), *aqkv = symp(g_aqkv), *ak = symp(g_ak), *av = symp(g_av);
    float *wkn = symp(g_wkn), *wvn = symp(g_wvn), *hid = symp(g_hid), *wk = symp(g_wk), *wv = symp(g_wv);
    float *pk = symp(g_pk), *pv = symp(g_pv), *q2a = symp(g_q2a), *q2 = symp(g_q2), *ybt = symp(g_ybt);

    cudaFuncSetAttribute(gemm_bf16s_kernel, cudaFuncAttributeMaxDynamicSharedMemorySize,
                         GEMM_SMEM_BYTES);
    cudaFuncSetAttribute(attn_mma_kernel, cudaFuncAttributeMaxDynamicSharedMemorySize,
                         ATTN_SMEM_BYTES);

    const int M = BB * TT;            // 2048
    const int MA = BB * AT;           // 3000

    // 1) qkv = x @ c_attn_w  (weights consumed in natural [K,N] layout)
    gemm_tc(x, c_attn_w, qkv, M, 3*CC, CC, nullptr, 0);

    // 2) split + rope
    {
        int tot = BB * TT * NH * 64;
        split_rope_kernel<<<(tot + 255) / 256, 256>>>(qkv, rope_cos, rope_sin, q, k, v);
    }

    // 3) causal self-attention -> y
    attn_mma_kernel<<<dim3(TT/64, NH, BB), 128, ATTN_SMEM_BYTES>>>(
        q, k, v, y, NH, TT, TT, (long)NH*TT*HS, (long)TT*HS, 1, nullptr, 0);

    // 4) adapter branch
    rmsnorm_kernel<<<ALEN, 256>>>(adapter, rms_gate, pref, CC);
    gemm_tc(pref, c_attn_w, aqkv, ALEN, 3*CC, CC, nullptr, 0);
    adapter_split_kernel<<<(NH*ALEN*HS + 255) / 256, 256>>>(aqkv, ak, av);
    attn_mma_kernel<<<dim3(TT/64, NH, BB), 128, ATTN_SMEM_BYTES>>>(
        q, ak, av, y, NH, TT, ALEN, 0L, (long)ALEN*HS, 0, gating, 1);

    // 5) whisper key path
    gemm_tc(audio, wkw, wkn, MA, AD, AD, nullptr, 0);
    rmsnorm_kernel<<<MA, 256>>>(wkn, rms_key, wkn, AD);
    gemm_tc(wkn, proj_dn, hid, MA, DHID, AD, nullptr, 1);
    gemm_tc(hid, proj_up, wk, MA, AD, DHID, nullptr, 0);

    // 6) whisper value path
    gemm_tc(audio, wvw, wvn, MA, AD, AD, wvb, 0);
    rmsnorm_kernel<<<MA, 256>>>(wvn, rms_val, wvn, AD);
    gemm_tc(wvn, proj_dn, hid, MA, DHID, AD, nullptr, 1);
    gemm_tc(hid, proj_up, wv, MA, AD, DHID, nullptr, 0);

    // 7) assemble pk/pv
    {
        int tot = BB * NH * AT * HS;
        fill_pkv_kernel<<<(tot + 255) / 256, 256>>>(wk, pad_k, pk);
        fill_pkv_kernel<<<(tot + 255) / 256, 256>>>(wv, pad_v, pv);
    }

    // 8) q2 = (q @ proj_q128) head-mixed by proj_q32
    gemm_tc(q, pq128, q2a, BB*NH*TT, HS, HS, nullptr, 0);
    headmix_kernel<<<BB * TT, 256>>>(q2a, pq32, q2);

    // 9) whisper cross-attention -> y += proj_gating * wy
    attn_mma_kernel<<<dim3(TT/64, NH, BB), 128, ATTN_SMEM_BYTES>>>(
        q2, pk, pv, y, NH, TT, AT, (long)NH*AT*HS, (long)AT*HS, 0, pgating, 1);

    // 10) transpose + output projection
    {
        int tot = BB * TT * CC;
        transpose_y_kernel<<<(tot + 255) / 256, 256>>>(y, ybt);
    }
    gemm_tc(ybt, c_proj_w, out, M, CC, CC, nullptr, 0);
}